// round 1
// baseline (speedup 1.0000x reference)
#include <cuda_runtime.h>
#include <math.h>

#define BB 2
#define TT 2048
#define DD 1024
#define NH 16
#define NG 4
#define HDIM 64
#define RR (BB*TT)   // 4096 rows

// -------- scratch (device globals; no runtime allocation) --------
__device__ float g_h1[RR*DD];
__device__ float g_q [RR*DD];
__device__ float g_k [RR*(NG*HDIM)];
__device__ float g_v [RR*(NG*HDIM)];
__device__ float g_ao[RR*DD];
__device__ float g_x1[RR*DD];
__device__ float g_h2[RR*DD];
__device__ float g_f1[RR*4*DD];

// ===================== LayerNorm =====================
__device__ __forceinline__ float block_sum256(float v, float* sh) {
    #pragma unroll
    for (int o = 16; o; o >>= 1) v += __shfl_xor_sync(0xffffffffu, v, o);
    if ((threadIdx.x & 31) == 0) sh[threadIdx.x >> 5] = v;
    __syncthreads();
    float t = sh[threadIdx.x & 7];
    #pragma unroll
    for (int o = 4; o; o >>= 1) t += __shfl_xor_sync(0xffffffffu, t, o);
    __syncthreads();   // safe reuse of sh
    return t;
}

__global__ void ln_kernel(const float* __restrict__ x, const float* __restrict__ gw,
                          const float* __restrict__ bw, float* __restrict__ out) {
    __shared__ float sh[8];
    const int row = blockIdx.x;
    const float4* xr = reinterpret_cast<const float4*>(x + (size_t)row * DD);
    float4 v = xr[threadIdx.x];
    float s = v.x + v.y + v.z + v.w;
    float tot = block_sum256(s, sh);
    float mean = tot * (1.0f / DD);
    float dx = v.x - mean, dy = v.y - mean, dz = v.z - mean, dw = v.w - mean;
    float s2 = dx*dx + dy*dy + dz*dz + dw*dw;
    float tot2 = block_sum256(s2, sh);
    float rstd = rsqrtf(tot2 * (1.0f / DD) + 1e-5f);
    float4 g4 = reinterpret_cast<const float4*>(gw)[threadIdx.x];
    float4 b4 = reinterpret_cast<const float4*>(bw)[threadIdx.x];
    float4 o;
    o.x = g4.x * dx * rstd + b4.x;
    o.y = g4.y * dy * rstd + b4.y;
    o.z = g4.z * dz * rstd + b4.z;
    o.w = g4.w * dw * rstd + b4.w;
    reinterpret_cast<float4*>(out + (size_t)row * DD)[threadIdx.x] = o;
}

// ===================== SGEMM (128x128x8, 256 thr, 8x8/thr) =====================
// C[M,N] = A[M,K] @ B[K,N] + bias  (+ optional GELU or residual)
// EPI: 0 = none, 1 = exact-erf GELU, 2 = += res
template<int EPI>
__global__ void __launch_bounds__(256, 2)
sgemm_kernel(const float* __restrict__ A, const float* __restrict__ Bm,
             const float* __restrict__ bias, const float* __restrict__ res,
             float* __restrict__ C, int M, int N, int K) {
    __shared__ float As[8][128];
    __shared__ float Bs[8][128];
    const int tid  = threadIdx.x;
    const int brow = blockIdx.y * 128, bcol = blockIdx.x * 128;
    const int aRow = tid >> 1,  aCol = (tid & 1)  << 2;
    const int bRow = tid >> 5,  bCol = (tid & 31) << 2;
    const int tr   = (tid >> 4) << 3, tc = (tid & 15) << 3;

    float acc[8][8];
    #pragma unroll
    for (int i = 0; i < 8; i++)
        #pragma unroll
        for (int j = 0; j < 8; j++) acc[i][j] = 0.0f;

    const float* Aptr = A  + (size_t)(brow + aRow) * K + aCol;
    const float* Bptr = Bm + (size_t)bRow * N + bcol + bCol;

    for (int k0 = 0; k0 < K; k0 += 8) {
        float4 a = *reinterpret_cast<const float4*>(Aptr + k0);
        As[aCol + 0][aRow] = a.x;
        As[aCol + 1][aRow] = a.y;
        As[aCol + 2][aRow] = a.z;
        As[aCol + 3][aRow] = a.w;
        float4 b4 = *reinterpret_cast<const float4*>(Bptr + (size_t)k0 * N);
        *reinterpret_cast<float4*>(&Bs[bRow][bCol]) = b4;
        __syncthreads();
        #pragma unroll
        for (int k = 0; k < 8; k++) {
            float ra[8], rb[8];
            #pragma unroll
            for (int i = 0; i < 8; i++) ra[i] = As[k][tr + i];
            #pragma unroll
            for (int j = 0; j < 8; j++) rb[j] = Bs[k][tc + j];
            #pragma unroll
            for (int i = 0; i < 8; i++)
                #pragma unroll
                for (int j = 0; j < 8; j++)
                    acc[i][j] = fmaf(ra[i], rb[j], acc[i][j]);
        }
        __syncthreads();
    }

    #pragma unroll
    for (int i = 0; i < 8; i++) {
        const int grow = brow + tr + i;
        float* Crow = C + (size_t)grow * N + bcol;
        const float* Rrow = (EPI == 2) ? (res + (size_t)grow * N + bcol) : nullptr;
        #pragma unroll
        for (int j = 0; j < 8; j++) {
            float vv = acc[i][j] + bias[bcol + tc + j];
            if (EPI == 1) vv = 0.5f * vv * (1.0f + erff(vv * 0.70710678118654752f));
            if (EPI == 2) vv += Rrow[tc + j];
            Crow[tc + j] = vv;
        }
    }
}

// ===================== Flash attention (fp32, causal, GQA) =====================
// Q: [R, D] (col = h*64+hd), K/V: [R, 256] (col = g*64+hd)
// grid: (T/64, NH, B), 256 threads, dyn smem = 4 * 64*65 * 4 B
__global__ void __launch_bounds__(256, 3)
attn_kernel(const float* __restrict__ Q, const float* __restrict__ K,
            const float* __restrict__ V, float* __restrict__ O) {
    extern __shared__ float sm[];
    float (*Qs)[65] = reinterpret_cast<float(*)[65]>(sm);
    float (*Ks)[65] = reinterpret_cast<float(*)[65]>(sm + 64 * 65);
    float (*Vs)[65] = reinterpret_cast<float(*)[65]>(sm + 2 * 64 * 65);
    float (*Ps)[65] = reinterpret_cast<float(*)[65]>(sm + 3 * 64 * 65);

    const int tid = threadIdx.x;
    const int h = blockIdx.y, b = blockIdx.z, g = h >> 2;
    const int q0 = blockIdx.x << 6;

    // load Q tile (64 x 64)
    {
        const size_t qbase = (size_t)(b * TT + q0) * DD + h * 64;
        for (int i = tid; i < 64 * 16; i += 256) {
            int r = i >> 4, c = (i & 15) << 2;
            float4 v4 = *reinterpret_cast<const float4*>(Q + qbase + (size_t)r * DD + c);
            Qs[r][c] = v4.x; Qs[r][c+1] = v4.y; Qs[r][c+2] = v4.z; Qs[r][c+3] = v4.w;
        }
    }

    const int ty = tid >> 4, tx = tid & 15;
    const int r0 = ty << 2, c0 = tx << 2;

    float o[4][4];
    #pragma unroll
    for (int i = 0; i < 4; i++)
        #pragma unroll
        for (int j = 0; j < 4; j++) o[i][j] = 0.0f;
    float mrow[4] = {-1e30f, -1e30f, -1e30f, -1e30f};
    float lrow[4] = {0.0f, 0.0f, 0.0f, 0.0f};

    const int jmax = blockIdx.x;
    for (int jt = 0; jt <= jmax; jt++) {
        __syncthreads();   // prior Vs/Ps reads done (iter0: Q load done)
        // load K/V tiles (64 rows x 64 cols)
        const size_t kvbase = (size_t)(b * TT + (jt << 6)) * 256 + g * 64;
        for (int i = tid; i < 64 * 16; i += 256) {
            int r = i >> 4, c = (i & 15) << 2;
            float4 kk = *reinterpret_cast<const float4*>(K + kvbase + (size_t)r * 256 + c);
            Ks[r][c] = kk.x; Ks[r][c+1] = kk.y; Ks[r][c+2] = kk.z; Ks[r][c+3] = kk.w;
            float4 vv = *reinterpret_cast<const float4*>(V + kvbase + (size_t)r * 256 + c);
            Vs[r][c] = vv.x; Vs[r][c+1] = vv.y; Vs[r][c+2] = vv.z; Vs[r][c+3] = vv.w;
        }
        __syncthreads();

        // S = Q K^T (4x4 micro-tile per thread)
        float s[4][4];
        #pragma unroll
        for (int i = 0; i < 4; i++)
            #pragma unroll
            for (int j = 0; j < 4; j++) s[i][j] = 0.0f;
        #pragma unroll 16
        for (int k = 0; k < 64; k++) {
            float qv[4], kv[4];
            #pragma unroll
            for (int i = 0; i < 4; i++) qv[i] = Qs[r0 + i][k];
            #pragma unroll
            for (int j = 0; j < 4; j++) kv[j] = Ks[c0 + j][k];
            #pragma unroll
            for (int i = 0; i < 4; i++)
                #pragma unroll
                for (int j = 0; j < 4; j++)
                    s[i][j] = fmaf(qv[i], kv[j], s[i][j]);
        }

        const bool diag = (jt == jmax);
        #pragma unroll
        for (int i = 0; i < 4; i++) {
            const int qi = q0 + r0 + i;
            float tm = -1e30f;
            #pragma unroll
            for (int j = 0; j < 4; j++) {
                float sv = s[i][j] * 0.125f;
                if (diag && ((jt << 6) + c0 + j > qi)) sv = -1e30f;
                s[i][j] = sv;
                tm = fmaxf(tm, sv);
            }
            #pragma unroll
            for (int off = 8; off; off >>= 1)
                tm = fmaxf(tm, __shfl_xor_sync(0xffffffffu, tm, off, 16));
            const float newm = fmaxf(mrow[i], tm);
            const float alpha = __expf(mrow[i] - newm);
            mrow[i] = newm;
            float ts = 0.0f;
            #pragma unroll
            for (int j = 0; j < 4; j++) {
                float p = __expf(s[i][j] - newm);
                s[i][j] = p;
                ts += p;
            }
            #pragma unroll
            for (int off = 8; off; off >>= 1)
                ts += __shfl_xor_sync(0xffffffffu, ts, off, 16);
            lrow[i] = lrow[i] * alpha + ts;
            #pragma unroll
            for (int j = 0; j < 4; j++) o[i][j] *= alpha;
            #pragma unroll
            for (int j = 0; j < 4; j++) Ps[r0 + i][c0 + j] = s[i][j];
        }
        __syncthreads();

        // O += P @ V
        #pragma unroll 16
        for (int k = 0; k < 64; k++) {
            float pv[4], vv[4];
            #pragma unroll
            for (int i = 0; i < 4; i++) pv[i] = Ps[r0 + i][k];
            #pragma unroll
            for (int j = 0; j < 4; j++) vv[j] = Vs[k][c0 + j];
            #pragma unroll
            for (int i = 0; i < 4; i++)
                #pragma unroll
                for (int j = 0; j < 4; j++)
                    o[i][j] = fmaf(pv[i], vv[j], o[i][j]);
        }
    }

    // write out
    #pragma unroll
    for (int i = 0; i < 4; i++) {
        const float inv = 1.0f / lrow[i];
        const size_t obase = (size_t)(b * TT + q0 + r0 + i) * DD + h * 64 + c0;
        #pragma unroll
        for (int j = 0; j < 4; j++)
            O[obase + j] = o[i][j] * inv;
    }
}

// ===================== launch =====================
extern "C" void kernel_launch(void* const* d_in, const int* in_sizes, int n_in,
                              void* d_out, int out_size) {
    (void)in_sizes; (void)n_in; (void)out_size;
    const float* x   = (const float*)d_in[0];
    const float* g1  = (const float*)d_in[1];
    const float* bt1 = (const float*)d_in[2];
    const float* wq  = (const float*)d_in[3];
    const float* bq  = (const float*)d_in[4];
    const float* wk  = (const float*)d_in[5];
    const float* bk  = (const float*)d_in[6];
    const float* wv  = (const float*)d_in[7];
    const float* bv  = (const float*)d_in[8];
    const float* wo  = (const float*)d_in[9];
    const float* bo  = (const float*)d_in[10];
    const float* g2  = (const float*)d_in[11];
    const float* bt2 = (const float*)d_in[12];
    const float* w1  = (const float*)d_in[13];
    const float* b1  = (const float*)d_in[14];
    const float* w2  = (const float*)d_in[15];
    const float* b2  = (const float*)d_in[16];
    float* out = (float*)d_out;

    float *h1, *q, *k, *v, *ao, *x1, *h2, *f1;
    cudaGetSymbolAddress((void**)&h1, g_h1);
    cudaGetSymbolAddress((void**)&q,  g_q);
    cudaGetSymbolAddress((void**)&k,  g_k);
    cudaGetSymbolAddress((void**)&v,  g_v);
    cudaGetSymbolAddress((void**)&ao, g_ao);
    cudaGetSymbolAddress((void**)&x1, g_x1);
    cudaGetSymbolAddress((void**)&h2, g_h2);
    cudaGetSymbolAddress((void**)&f1, g_f1);

    const int ATTN_SMEM = 4 * 64 * 65 * (int)sizeof(float);
    cudaFuncSetAttribute(attn_kernel, cudaFuncAttributeMaxDynamicSharedMemorySize, ATTN_SMEM);

    // 1. h1 = LN(x)
    ln_kernel<<<RR, 256>>>(x, g1, bt1, h1);
    // 2. q/k/v projections
    sgemm_kernel<0><<<dim3(DD / 128, RR / 128), 256>>>(h1, wq, bq, nullptr, q, RR, DD, DD);
    sgemm_kernel<0><<<dim3(256 / 128, RR / 128), 256>>>(h1, wk, bk, nullptr, k, RR, 256, DD);
    sgemm_kernel<0><<<dim3(256 / 128, RR / 128), 256>>>(h1, wv, bv, nullptr, v, RR, 256, DD);
    // 3. attention
    attn_kernel<<<dim3(TT / 64, NH, BB), 256, ATTN_SMEM>>>(q, k, v, ao);
    // 4. x1 = x + ao @ wo + bo
    sgemm_kernel<2><<<dim3(DD / 128, RR / 128), 256>>>(ao, wo, bo, x, x1, RR, DD, DD);
    // 5. h2 = LN(x1)
    ln_kernel<<<RR, 256>>>(x1, g2, bt2, h2);
    // 6. f1 = gelu(h2 @ w1 + b1)
    sgemm_kernel<1><<<dim3(4 * DD / 128, RR / 128), 256>>>(h2, w1, b1, nullptr, f1, RR, 4 * DD, DD);
    // 7. out = x1 + f1 @ w2 + b2
    sgemm_kernel<2><<<dim3(DD / 128, RR / 128), 256>>>(f1, w2, b2, x1, out, RR, DD, 4 * DD);
}

// round 2
// speedup vs baseline: 2.1469x; 2.1469x over previous
#include <cuda_runtime.h>
#include <math.h>
#include <stdint.h>

#define BB 2
#define TT 2048
#define DD 1024
#define RR (BB*TT)   // 4096 rows

// -------- scratch (device globals; no runtime allocation) --------
__device__ float g_h1[RR*DD];
__device__ float g_q [RR*DD];
__device__ float g_k [RR*256];
__device__ float g_v [RR*256];
__device__ float g_ao[RR*DD];
__device__ float g_x1[RR*DD];
__device__ float g_h2[RR*DD];
__device__ float g_f1[RR*4*DD];

// ===================== LayerNorm =====================
__device__ __forceinline__ float block_sum256(float v, float* sh) {
    #pragma unroll
    for (int o = 16; o; o >>= 1) v += __shfl_xor_sync(0xffffffffu, v, o);
    if ((threadIdx.x & 31) == 0) sh[threadIdx.x >> 5] = v;
    __syncthreads();
    float t = sh[threadIdx.x & 7];
    #pragma unroll
    for (int o = 4; o; o >>= 1) t += __shfl_xor_sync(0xffffffffu, t, o);
    __syncthreads();
    return t;
}

__global__ void ln_kernel(const float* __restrict__ x, const float* __restrict__ gw,
                          const float* __restrict__ bw, float* __restrict__ out) {
    __shared__ float sh[8];
    const int row = blockIdx.x;
    const float4* xr = reinterpret_cast<const float4*>(x + (size_t)row * DD);
    float4 v = xr[threadIdx.x];
    float s = v.x + v.y + v.z + v.w;
    float tot = block_sum256(s, sh);
    float mean = tot * (1.0f / DD);
    float dx = v.x - mean, dy = v.y - mean, dz = v.z - mean, dw = v.w - mean;
    float s2 = dx*dx + dy*dy + dz*dz + dw*dw;
    float tot2 = block_sum256(s2, sh);
    float rstd = rsqrtf(tot2 * (1.0f / DD) + 1e-5f);
    float4 g4 = reinterpret_cast<const float4*>(gw)[threadIdx.x];
    float4 b4 = reinterpret_cast<const float4*>(bw)[threadIdx.x];
    float4 o;
    o.x = g4.x * dx * rstd + b4.x;
    o.y = g4.y * dy * rstd + b4.y;
    o.z = g4.z * dz * rstd + b4.z;
    o.w = g4.w * dw * rstd + b4.w;
    reinterpret_cast<float4*>(out + (size_t)row * DD)[threadIdx.x] = o;
}

// ===================== TF32 tensor-core GEMM =====================
// C[M,N] = A[M,K] @ B[K,N] + bias (+ GELU or residual)
// 128x128x16 CTA tile, 8 warps (2x4), warp tile 64x32, mma.m16n8k8.tf32.
// EPI: 0 = none, 1 = exact-erf GELU, 2 = += res

__device__ __forceinline__ uint32_t f2tf(float f) {
    uint32_t u;
    asm("cvt.rna.tf32.f32 %0, %1;" : "=r"(u) : "f"(f));
    return u;
}

#define ASTRIDE 20    // bank = (m*20+k)%32 distinct over m0..7 x k0..3
#define BSTRIDE 136   // bank = (k*8+n)%32 distinct over k0..3 x n0..7

template<int EPI>
__global__ void __launch_bounds__(256, 2)
gemm_tf32(const float* __restrict__ A, const float* __restrict__ Bm,
          const float* __restrict__ bias, const float* __restrict__ res,
          float* __restrict__ C, int M, int N, int K) {
    __shared__ uint32_t As[2][128 * ASTRIDE];
    __shared__ uint32_t Bs[2][16 * BSTRIDE];

    const int tid  = threadIdx.x;
    const int lane = tid & 31, wid = tid >> 5;
    const int wm = wid & 1, wn = wid >> 1;     // 2 x 4 warp grid
    const int g  = lane >> 2, tg = lane & 3;
    const int brow = blockIdx.y * 128, bcol = blockIdx.x * 128;

    float acc[4][4][4];
    #pragma unroll
    for (int mt = 0; mt < 4; mt++)
        #pragma unroll
        for (int nt = 0; nt < 4; nt++)
            #pragma unroll
            for (int c = 0; c < 4; c++) acc[mt][nt][c] = 0.0f;

    // ---- prologue: load tile 0 ----
    {
        #pragma unroll
        for (int r = 0; r < 2; r++) {
            const int f = tid + (r << 8);
            const int arow = f >> 2, akc = (f & 3) << 2;
            float4 ra = *reinterpret_cast<const float4*>(A + (size_t)(brow + arow) * K + akc);
            uint4 ua = { f2tf(ra.x), f2tf(ra.y), f2tf(ra.z), f2tf(ra.w) };
            *reinterpret_cast<uint4*>(&As[0][arow * ASTRIDE + akc]) = ua;
            const int bk = f >> 5, bn = (f & 31) << 2;
            float4 rb = *reinterpret_cast<const float4*>(Bm + (size_t)bk * N + bcol + bn);
            uint4 ub = { f2tf(rb.x), f2tf(rb.y), f2tf(rb.z), f2tf(rb.w) };
            *reinterpret_cast<uint4*>(&Bs[0][bk * BSTRIDE + bn]) = ub;
        }
    }
    __syncthreads();

    const int nk = K >> 4;
    float4 ra[2], rb[2];
    for (int kt = 0; kt < nk; kt++) {
        const int cur = kt & 1;
        if (kt + 1 < nk) {
            const int k0 = (kt + 1) << 4;
            #pragma unroll
            for (int r = 0; r < 2; r++) {
                const int f = tid + (r << 8);
                const int arow = f >> 2, akc = (f & 3) << 2;
                ra[r] = *reinterpret_cast<const float4*>(A + (size_t)(brow + arow) * K + k0 + akc);
                const int bk = f >> 5, bn = (f & 31) << 2;
                rb[r] = *reinterpret_cast<const float4*>(Bm + (size_t)(k0 + bk) * N + bcol + bn);
            }
        }
        // ---- compute on buffer `cur` ----
        #pragma unroll
        for (int ks = 0; ks < 2; ks++) {
            uint32_t afr[4][4], bfr[4][2];
            const int kk = ks * 8 + tg;
            #pragma unroll
            for (int mt = 0; mt < 4; mt++) {
                const int base = (wm * 64 + mt * 16 + g) * ASTRIDE + kk;
                afr[mt][0] = As[cur][base];
                afr[mt][1] = As[cur][base + 8 * ASTRIDE];
                afr[mt][2] = As[cur][base + 4];
                afr[mt][3] = As[cur][base + 8 * ASTRIDE + 4];
            }
            #pragma unroll
            for (int nt = 0; nt < 4; nt++) {
                const int nc = wn * 32 + nt * 8 + g;
                bfr[nt][0] = Bs[cur][(ks * 8 + tg) * BSTRIDE + nc];
                bfr[nt][1] = Bs[cur][(ks * 8 + tg + 4) * BSTRIDE + nc];
            }
            #pragma unroll
            for (int mt = 0; mt < 4; mt++)
                #pragma unroll
                for (int nt = 0; nt < 4; nt++)
                    asm volatile(
                        "mma.sync.aligned.m16n8k8.row.col.f32.tf32.tf32.f32 "
                        "{%0,%1,%2,%3}, {%4,%5,%6,%7}, {%8,%9}, {%0,%1,%2,%3};"
                        : "+f"(acc[mt][nt][0]), "+f"(acc[mt][nt][1]),
                          "+f"(acc[mt][nt][2]), "+f"(acc[mt][nt][3])
                        : "r"(afr[mt][0]), "r"(afr[mt][1]),
                          "r"(afr[mt][2]), "r"(afr[mt][3]),
                          "r"(bfr[nt][0]), "r"(bfr[nt][1]));
        }
        if (kt + 1 < nk) {
            const int nxt = cur ^ 1;
            #pragma unroll
            for (int r = 0; r < 2; r++) {
                const int f = tid + (r << 8);
                const int arow = f >> 2, akc = (f & 3) << 2;
                uint4 ua = { f2tf(ra[r].x), f2tf(ra[r].y), f2tf(ra[r].z), f2tf(ra[r].w) };
                *reinterpret_cast<uint4*>(&As[nxt][arow * ASTRIDE + akc]) = ua;
                const int bk = f >> 5, bn = (f & 31) << 2;
                uint4 ub = { f2tf(rb[r].x), f2tf(rb[r].y), f2tf(rb[r].z), f2tf(rb[r].w) };
                *reinterpret_cast<uint4*>(&Bs[nxt][bk * BSTRIDE + bn]) = ub;
            }
        }
        __syncthreads();
    }

    // ---- epilogue ----
    #pragma unroll
    for (int mt = 0; mt < 4; mt++) {
        #pragma unroll
        for (int half = 0; half < 2; half++) {
            const int row = brow + wm * 64 + mt * 16 + g + half * 8;
            float* Crow = C + (size_t)row * N;
            #pragma unroll
            for (int nt = 0; nt < 4; nt++) {
                const int col = bcol + wn * 32 + nt * 8 + tg * 2;
                float v0 = acc[mt][nt][half * 2 + 0] + bias[col];
                float v1 = acc[mt][nt][half * 2 + 1] + bias[col + 1];
                if (EPI == 1) {
                    v0 = 0.5f * v0 * (1.0f + erff(v0 * 0.70710678118654752f));
                    v1 = 0.5f * v1 * (1.0f + erff(v1 * 0.70710678118654752f));
                }
                if (EPI == 2) {
                    float2 rr = *reinterpret_cast<const float2*>(res + (size_t)row * N + col);
                    v0 += rr.x; v1 += rr.y;
                }
                float2 o2; o2.x = v0; o2.y = v1;
                *reinterpret_cast<float2*>(Crow + col) = o2;
            }
        }
    }
}

// ===================== Flash attention (fp32, causal, GQA) =====================
__global__ void __launch_bounds__(256, 3)
attn_kernel(const float* __restrict__ Q, const float* __restrict__ K,
            const float* __restrict__ V, float* __restrict__ O) {
    extern __shared__ float sm[];
    float (*Qs)[65] = reinterpret_cast<float(*)[65]>(sm);
    float (*Ks)[65] = reinterpret_cast<float(*)[65]>(sm + 64 * 65);
    float (*Vs)[65] = reinterpret_cast<float(*)[65]>(sm + 2 * 64 * 65);
    float (*Ps)[65] = reinterpret_cast<float(*)[65]>(sm + 3 * 64 * 65);

    const int tid = threadIdx.x;
    const int h = blockIdx.y, b = blockIdx.z, g = h >> 2;
    const int q0 = blockIdx.x << 6;

    {
        const size_t qbase = (size_t)(b * TT + q0) * DD + h * 64;
        for (int i = tid; i < 64 * 16; i += 256) {
            int r = i >> 4, c = (i & 15) << 2;
            float4 v4 = *reinterpret_cast<const float4*>(Q + qbase + (size_t)r * DD + c);
            Qs[r][c] = v4.x; Qs[r][c+1] = v4.y; Qs[r][c+2] = v4.z; Qs[r][c+3] = v4.w;
        }
    }

    const int ty = tid >> 4, tx = tid & 15;
    const int r0 = ty << 2, c0 = tx << 2;

    float o[4][4];
    #pragma unroll
    for (int i = 0; i < 4; i++)
        #pragma unroll
        for (int j = 0; j < 4; j++) o[i][j] = 0.0f;
    float mrow[4] = {-1e30f, -1e30f, -1e30f, -1e30f};
    float lrow[4] = {0.0f, 0.0f, 0.0f, 0.0f};

    const int jmax = blockIdx.x;
    for (int jt = 0; jt <= jmax; jt++) {
        __syncthreads();
        const size_t kvbase = (size_t)(b * TT + (jt << 6)) * 256 + g * 64;
        for (int i = tid; i < 64 * 16; i += 256) {
            int r = i >> 4, c = (i & 15) << 2;
            float4 kk = *reinterpret_cast<const float4*>(K + kvbase + (size_t)r * 256 + c);
            Ks[r][c] = kk.x; Ks[r][c+1] = kk.y; Ks[r][c+2] = kk.z; Ks[r][c+3] = kk.w;
            float4 vv = *reinterpret_cast<const float4*>(V + kvbase + (size_t)r * 256 + c);
            Vs[r][c] = vv.x; Vs[r][c+1] = vv.y; Vs[r][c+2] = vv.z; Vs[r][c+3] = vv.w;
        }
        __syncthreads();

        float s[4][4];
        #pragma unroll
        for (int i = 0; i < 4; i++)
            #pragma unroll
            for (int j = 0; j < 4; j++) s[i][j] = 0.0f;
        #pragma unroll 16
        for (int k = 0; k < 64; k++) {
            float qv[4], kv[4];
            #pragma unroll
            for (int i = 0; i < 4; i++) qv[i] = Qs[r0 + i][k];
            #pragma unroll
            for (int j = 0; j < 4; j++) kv[j] = Ks[c0 + j][k];
            #pragma unroll
            for (int i = 0; i < 4; i++)
                #pragma unroll
                for (int j = 0; j < 4; j++)
                    s[i][j] = fmaf(qv[i], kv[j], s[i][j]);
        }

        const bool diag = (jt == jmax);
        #pragma unroll
        for (int i = 0; i < 4; i++) {
            const int qi = q0 + r0 + i;
            float tm = -1e30f;
            #pragma unroll
            for (int j = 0; j < 4; j++) {
                float sv = s[i][j] * 0.125f;
                if (diag && ((jt << 6) + c0 + j > qi)) sv = -1e30f;
                s[i][j] = sv;
                tm = fmaxf(tm, sv);
            }
            #pragma unroll
            for (int off = 8; off; off >>= 1)
                tm = fmaxf(tm, __shfl_xor_sync(0xffffffffu, tm, off, 16));
            const float newm = fmaxf(mrow[i], tm);
            const float alpha = __expf(mrow[i] - newm);
            mrow[i] = newm;
            float ts = 0.0f;
            #pragma unroll
            for (int j = 0; j < 4; j++) {
                float p = __expf(s[i][j] - newm);
                s[i][j] = p;
                ts += p;
            }
            #pragma unroll
            for (int off = 8; off; off >>= 1)
                ts += __shfl_xor_sync(0xffffffffu, ts, off, 16);
            lrow[i] = lrow[i] * alpha + ts;
            #pragma unroll
            for (int j = 0; j < 4; j++) o[i][j] *= alpha;
            #pragma unroll
            for (int j = 0; j < 4; j++) Ps[r0 + i][c0 + j] = s[i][j];
        }
        __syncthreads();

        #pragma unroll 16
        for (int k = 0; k < 64; k++) {
            float pv[4], vv[4];
            #pragma unroll
            for (int i = 0; i < 4; i++) pv[i] = Ps[r0 + i][k];
            #pragma unroll
            for (int j = 0; j < 4; j++) vv[j] = Vs[k][c0 + j];
            #pragma unroll
            for (int i = 0; i < 4; i++)
                #pragma unroll
                for (int j = 0; j < 4; j++)
                    o[i][j] = fmaf(pv[i], vv[j], o[i][j]);
        }
    }

    #pragma unroll
    for (int i = 0; i < 4; i++) {
        const float inv = 1.0f / lrow[i];
        const size_t obase = (size_t)(b * TT + q0 + r0 + i) * DD + h * 64 + c0;
        #pragma unroll
        for (int j = 0; j < 4; j++)
            O[obase + j] = o[i][j] * inv;
    }
}

// ===================== launch =====================
extern "C" void kernel_launch(void* const* d_in, const int* in_sizes, int n_in,
                              void* d_out, int out_size) {
    (void)in_sizes; (void)n_in; (void)out_size;
    const float* x   = (const float*)d_in[0];
    const float* g1  = (const float*)d_in[1];
    const float* bt1 = (const float*)d_in[2];
    const float* wq  = (const float*)d_in[3];
    const float* bq  = (const float*)d_in[4];
    const float* wk  = (const float*)d_in[5];
    const float* bk  = (const float*)d_in[6];
    const float* wv  = (const float*)d_in[7];
    const float* bv  = (const float*)d_in[8];
    const float* wo  = (const float*)d_in[9];
    const float* bo  = (const float*)d_in[10];
    const float* g2  = (const float*)d_in[11];
    const float* bt2 = (const float*)d_in[12];
    const float* w1  = (const float*)d_in[13];
    const float* b1  = (const float*)d_in[14];
    const float* w2  = (const float*)d_in[15];
    const float* b2  = (const float*)d_in[16];
    float* out = (float*)d_out;

    float *h1, *q, *k, *v, *ao, *x1, *h2, *f1;
    cudaGetSymbolAddress((void**)&h1, g_h1);
    cudaGetSymbolAddress((void**)&q,  g_q);
    cudaGetSymbolAddress((void**)&k,  g_k);
    cudaGetSymbolAddress((void**)&v,  g_v);
    cudaGetSymbolAddress((void**)&ao, g_ao);
    cudaGetSymbolAddress((void**)&x1, g_x1);
    cudaGetSymbolAddress((void**)&h2, g_h2);
    cudaGetSymbolAddress((void**)&f1, g_f1);

    const int ATTN_SMEM = 4 * 64 * 65 * (int)sizeof(float);
    cudaFuncSetAttribute(attn_kernel, cudaFuncAttributeMaxDynamicSharedMemorySize, ATTN_SMEM);

    // 1. h1 = LN(x)
    ln_kernel<<<RR, 256>>>(x, g1, bt1, h1);
    // 2. q/k/v projections (tf32 tensor cores)
    gemm_tf32<0><<<dim3(DD / 128, RR / 128), 256>>>(h1, wq, bq, nullptr, q, RR, DD, DD);
    gemm_tf32<0><<<dim3(256 / 128, RR / 128), 256>>>(h1, wk, bk, nullptr, k, RR, 256, DD);
    gemm_tf32<0><<<dim3(256 / 128, RR / 128), 256>>>(h1, wv, bv, nullptr, v, RR, 256, DD);
    // 3. attention
    attn_kernel<<<dim3(TT / 64, 16, BB), 256, ATTN_SMEM>>>(q, k, v, ao);
    // 4. x1 = x + ao @ wo + bo
    gemm_tf32<2><<<dim3(DD / 128, RR / 128), 256>>>(ao, wo, bo, x, x1, RR, DD, DD);
    // 5. h2 = LN(x1)
    ln_kernel<<<RR, 256>>>(x1, g2, bt2, h2);
    // 6. f1 = gelu(h2 @ w1 + b1)
    gemm_tf32<1><<<dim3(4 * DD / 128, RR / 128), 256>>>(h2, w1, b1, nullptr, f1, RR, 4 * DD, DD);
    // 7. out = x1 + f1 @ w2 + b2
    gemm_tf32<2><<<dim3(DD / 128, RR / 128), 256>>>(f1, w2, b2, x1, out, RR, DD, 4 * DD);
}

// round 3
// speedup vs baseline: 3.3494x; 1.5601x over previous
#include <cuda_runtime.h>
#include <math.h>
#include <stdint.h>

#define BB 2
#define TT 2048
#define DD 1024
#define RR (BB*TT)   // 4096 rows

// -------- scratch (device globals; no runtime allocation) --------
__device__ float g_h1[RR*DD];
__device__ float g_q [RR*DD];
__device__ float g_k [RR*256];
__device__ float g_v [RR*256];
__device__ float g_ao[RR*DD];
__device__ float g_x1[RR*DD];
__device__ float g_h2[RR*DD];
__device__ float g_f1[RR*4*DD];

__device__ __forceinline__ uint32_t f2tf(float f) {
    uint32_t u;
    asm("cvt.rna.tf32.f32 %0, %1;" : "=r"(u) : "f"(f));
    return u;
}

// ===================== LayerNorm =====================
__device__ __forceinline__ float block_sum256(float v, float* sh) {
    #pragma unroll
    for (int o = 16; o; o >>= 1) v += __shfl_xor_sync(0xffffffffu, v, o);
    if ((threadIdx.x & 31) == 0) sh[threadIdx.x >> 5] = v;
    __syncthreads();
    float t = sh[threadIdx.x & 7];
    #pragma unroll
    for (int o = 4; o; o >>= 1) t += __shfl_xor_sync(0xffffffffu, t, o);
    __syncthreads();
    return t;
}

__global__ void ln_kernel(const float* __restrict__ x, const float* __restrict__ gw,
                          const float* __restrict__ bw, float* __restrict__ out) {
    __shared__ float sh[8];
    const int row = blockIdx.x;
    const float4* xr = reinterpret_cast<const float4*>(x + (size_t)row * DD);
    float4 v = xr[threadIdx.x];
    float s = v.x + v.y + v.z + v.w;
    float tot = block_sum256(s, sh);
    float mean = tot * (1.0f / DD);
    float dx = v.x - mean, dy = v.y - mean, dz = v.z - mean, dw = v.w - mean;
    float s2 = dx*dx + dy*dy + dz*dz + dw*dw;
    float tot2 = block_sum256(s2, sh);
    float rstd = rsqrtf(tot2 * (1.0f / DD) + 1e-5f);
    float4 g4 = reinterpret_cast<const float4*>(gw)[threadIdx.x];
    float4 b4 = reinterpret_cast<const float4*>(bw)[threadIdx.x];
    float4 o;
    o.x = g4.x * dx * rstd + b4.x;
    o.y = g4.y * dy * rstd + b4.y;
    o.z = g4.z * dz * rstd + b4.z;
    o.w = g4.w * dw * rstd + b4.w;
    reinterpret_cast<float4*>(out + (size_t)row * DD)[threadIdx.x] = o;
}

// ===================== TF32 tensor-core GEMM =====================
#define ASTRIDE 20
#define BSTRIDE 136

// core mainloop+epilogue shared by plain and fused-qkv variants
template<int EPI>
__device__ __forceinline__ void gemm_body(
    const float* __restrict__ A, const float* __restrict__ Bm,
    const float* __restrict__ bias, const float* __restrict__ res,
    float* __restrict__ C, int N, int K, int brow, int bcol,
    uint32_t (*As)[128 * ASTRIDE], uint32_t (*Bs)[16 * BSTRIDE]) {

    const int tid  = threadIdx.x;
    const int lane = tid & 31, wid = tid >> 5;
    const int wm = wid & 1, wn = wid >> 1;
    const int g  = lane >> 2, tg = lane & 3;

    float acc[4][4][4];
    #pragma unroll
    for (int mt = 0; mt < 4; mt++)
        #pragma unroll
        for (int nt = 0; nt < 4; nt++)
            #pragma unroll
            for (int c = 0; c < 4; c++) acc[mt][nt][c] = 0.0f;

    {
        #pragma unroll
        for (int r = 0; r < 2; r++) {
            const int f = tid + (r << 8);
            const int arow = f >> 2, akc = (f & 3) << 2;
            float4 ra = *reinterpret_cast<const float4*>(A + (size_t)(brow + arow) * K + akc);
            uint4 ua = { f2tf(ra.x), f2tf(ra.y), f2tf(ra.z), f2tf(ra.w) };
            *reinterpret_cast<uint4*>(&As[0][arow * ASTRIDE + akc]) = ua;
            const int bk = f >> 5, bn = (f & 31) << 2;
            float4 rb = *reinterpret_cast<const float4*>(Bm + (size_t)bk * N + bcol + bn);
            uint4 ub = { f2tf(rb.x), f2tf(rb.y), f2tf(rb.z), f2tf(rb.w) };
            *reinterpret_cast<uint4*>(&Bs[0][bk * BSTRIDE + bn]) = ub;
        }
    }
    __syncthreads();

    const int nk = K >> 4;
    float4 ra[2], rb[2];
    for (int kt = 0; kt < nk; kt++) {
        const int cur = kt & 1;
        if (kt + 1 < nk) {
            const int k0 = (kt + 1) << 4;
            #pragma unroll
            for (int r = 0; r < 2; r++) {
                const int f = tid + (r << 8);
                const int arow = f >> 2, akc = (f & 3) << 2;
                ra[r] = *reinterpret_cast<const float4*>(A + (size_t)(brow + arow) * K + k0 + akc);
                const int bk = f >> 5, bn = (f & 31) << 2;
                rb[r] = *reinterpret_cast<const float4*>(Bm + (size_t)(k0 + bk) * N + bcol + bn);
            }
        }
        #pragma unroll
        for (int ks = 0; ks < 2; ks++) {
            uint32_t afr[4][4], bfr[4][2];
            const int kk = ks * 8 + tg;
            #pragma unroll
            for (int mt = 0; mt < 4; mt++) {
                const int base = (wm * 64 + mt * 16 + g) * ASTRIDE + kk;
                afr[mt][0] = As[cur][base];
                afr[mt][1] = As[cur][base + 8 * ASTRIDE];
                afr[mt][2] = As[cur][base + 4];
                afr[mt][3] = As[cur][base + 8 * ASTRIDE + 4];
            }
            #pragma unroll
            for (int nt = 0; nt < 4; nt++) {
                const int nc = wn * 32 + nt * 8 + g;
                bfr[nt][0] = Bs[cur][(ks * 8 + tg) * BSTRIDE + nc];
                bfr[nt][1] = Bs[cur][(ks * 8 + tg + 4) * BSTRIDE + nc];
            }
            #pragma unroll
            for (int mt = 0; mt < 4; mt++)
                #pragma unroll
                for (int nt = 0; nt < 4; nt++)
                    asm volatile(
                        "mma.sync.aligned.m16n8k8.row.col.f32.tf32.tf32.f32 "
                        "{%0,%1,%2,%3}, {%4,%5,%6,%7}, {%8,%9}, {%0,%1,%2,%3};"
                        : "+f"(acc[mt][nt][0]), "+f"(acc[mt][nt][1]),
                          "+f"(acc[mt][nt][2]), "+f"(acc[mt][nt][3])
                        : "r"(afr[mt][0]), "r"(afr[mt][1]),
                          "r"(afr[mt][2]), "r"(afr[mt][3]),
                          "r"(bfr[nt][0]), "r"(bfr[nt][1]));
        }
        if (kt + 1 < nk) {
            const int nxt = cur ^ 1;
            #pragma unroll
            for (int r = 0; r < 2; r++) {
                const int f = tid + (r << 8);
                const int arow = f >> 2, akc = (f & 3) << 2;
                uint4 ua = { f2tf(ra[r].x), f2tf(ra[r].y), f2tf(ra[r].z), f2tf(ra[r].w) };
                *reinterpret_cast<uint4*>(&As[nxt][arow * ASTRIDE + akc]) = ua;
                const int bk = f >> 5, bn = (f & 31) << 2;
                uint4 ub = { f2tf(rb[r].x), f2tf(rb[r].y), f2tf(rb[r].z), f2tf(rb[r].w) };
                *reinterpret_cast<uint4*>(&Bs[nxt][bk * BSTRIDE + bn]) = ub;
            }
        }
        __syncthreads();
    }

    #pragma unroll
    for (int mt = 0; mt < 4; mt++) {
        #pragma unroll
        for (int half = 0; half < 2; half++) {
            const int row = brow + wm * 64 + mt * 16 + g + half * 8;
            float* Crow = C + (size_t)row * N;
            #pragma unroll
            for (int nt = 0; nt < 4; nt++) {
                const int col = bcol + wn * 32 + nt * 8 + tg * 2;
                float v0 = acc[mt][nt][half * 2 + 0] + bias[col];
                float v1 = acc[mt][nt][half * 2 + 1] + bias[col + 1];
                if (EPI == 1) {
                    v0 = 0.5f * v0 * (1.0f + erff(v0 * 0.70710678118654752f));
                    v1 = 0.5f * v1 * (1.0f + erff(v1 * 0.70710678118654752f));
                }
                if (EPI == 2) {
                    float2 rr = *reinterpret_cast<const float2*>(res + (size_t)row * N + col);
                    v0 += rr.x; v1 += rr.y;
                }
                float2 o2; o2.x = v0; o2.y = v1;
                *reinterpret_cast<float2*>(Crow + col) = o2;
            }
        }
    }
}

template<int EPI>
__global__ void __launch_bounds__(256, 2)
gemm_tf32(const float* __restrict__ A, const float* __restrict__ Bm,
          const float* __restrict__ bias, const float* __restrict__ res,
          float* __restrict__ C, int M, int N, int K) {
    __shared__ uint32_t As[2][128 * ASTRIDE];
    __shared__ uint32_t Bs[2][16 * BSTRIDE];
    gemm_body<EPI>(A, Bm, bias, res, C, N, K, blockIdx.y * 128, blockIdx.x * 128, As, Bs);
}

// fused QKV: grid.x = 12 (8 q tiles, 2 k tiles, 2 v tiles)
__global__ void __launch_bounds__(256, 2)
gemm_qkv(const float* __restrict__ A,
         const float* __restrict__ wq, const float* __restrict__ bq,
         const float* __restrict__ wk, const float* __restrict__ bk,
         const float* __restrict__ wv, const float* __restrict__ bv,
         float* __restrict__ q, float* __restrict__ k, float* __restrict__ v) {
    __shared__ uint32_t As[2][128 * ASTRIDE];
    __shared__ uint32_t Bs[2][16 * BSTRIDE];
    const int bx = blockIdx.x;
    const float *Bm, *bias; float* C; int N, bcol;
    if (bx < 8)       { Bm = wq; bias = bq; C = q; N = 1024; bcol = bx * 128; }
    else if (bx < 10) { Bm = wk; bias = bk; C = k; N = 256;  bcol = (bx - 8) * 128; }
    else              { Bm = wv; bias = bv; C = v; N = 256;  bcol = (bx - 10) * 128; }
    gemm_body<0>(A, Bm, bias, nullptr, C, N, DD, blockIdx.y * 128, bcol, As, Bs);
}

// ===================== Flash attention (tf32 tensor cores, causal, GQA) =====================
// grid (T/64, 16, B), 128 threads (4 warps, each owns 16 q rows)
#define QS_S 68
#define KS_S 68
#define VS_S 72
#define PS_S 68
#define QS_OFF 0
#define KS_OFF (64*QS_S)
#define VS_OFF (KS_OFF + 64*KS_S)
#define PS_OFF (VS_OFF + 64*VS_S)
#define ATTN_WORDS (PS_OFF + 64*PS_S)

__global__ void __launch_bounds__(128, 3)
attn_mma(const float* __restrict__ Q, const float* __restrict__ K,
         const float* __restrict__ V, float* __restrict__ O) {
    extern __shared__ uint32_t sm[];
    uint32_t* Qs = sm + QS_OFF;
    uint32_t* Ks = sm + KS_OFF;
    uint32_t* Vs = sm + VS_OFF;
    uint32_t* Ps = sm + PS_OFF;

    const int tid = threadIdx.x;
    const int lane = tid & 31, w = tid >> 5;
    const int g = lane >> 2, tg = lane & 3;
    const int h = blockIdx.y, b = blockIdx.z, grp = h >> 2;
    const int q0 = blockIdx.x << 6;

    // load Q tile (scaled by 1/sqrt(64)=0.125, cvt tf32)
    {
        const size_t qbase = (size_t)(b * TT + q0) * DD + h * 64;
        #pragma unroll
        for (int it = 0; it < 8; it++) {
            const int i = tid + it * 128;
            const int r = i >> 4, c = (i & 15) << 2;
            float4 v4 = *reinterpret_cast<const float4*>(Q + qbase + (size_t)r * DD + c);
            uint4 u = { f2tf(v4.x * 0.125f), f2tf(v4.y * 0.125f),
                        f2tf(v4.z * 0.125f), f2tf(v4.w * 0.125f) };
            *reinterpret_cast<uint4*>(&Qs[r * QS_S + c]) = u;
        }
    }

    float oacc[8][4];
    #pragma unroll
    for (int nt = 0; nt < 8; nt++)
        #pragma unroll
        for (int c = 0; c < 4; c++) oacc[nt][c] = 0.0f;
    float m0 = -1e30f, m1 = -1e30f, l0 = 0.0f, l1 = 0.0f;

    const int row0 = q0 + w * 16 + g;      // absolute q row (first)
    const int row1 = row0 + 8;             // second

    const int jmax = blockIdx.x;
    for (int jt = 0; jt <= jmax; jt++) {
        __syncthreads();
        // load K/V tiles as tf32
        {
            const size_t kvbase = (size_t)(b * TT + (jt << 6)) * 256 + grp * 64;
            #pragma unroll
            for (int it = 0; it < 8; it++) {
                const int i = tid + it * 128;
                const int r = i >> 4, c = (i & 15) << 2;
                float4 kk = *reinterpret_cast<const float4*>(K + kvbase + (size_t)r * 256 + c);
                uint4 uk = { f2tf(kk.x), f2tf(kk.y), f2tf(kk.z), f2tf(kk.w) };
                *reinterpret_cast<uint4*>(&Ks[r * KS_S + c]) = uk;
                float4 vv = *reinterpret_cast<const float4*>(V + kvbase + (size_t)r * 256 + c);
                uint4 uv = { f2tf(vv.x), f2tf(vv.y), f2tf(vv.z), f2tf(vv.w) };
                *reinterpret_cast<uint4*>(&Vs[r * VS_S + c]) = uv;
            }
        }
        __syncthreads();

        // ---- S = Q_w (16x64) @ K^T (64x64) ----
        float sacc[8][4];
        #pragma unroll
        for (int nt = 0; nt < 8; nt++)
            #pragma unroll
            for (int c = 0; c < 4; c++) sacc[nt][c] = 0.0f;
        #pragma unroll
        for (int ks = 0; ks < 8; ks++) {
            const int abase = (w * 16 + g) * QS_S + ks * 8 + tg;
            uint32_t a0 = Qs[abase];
            uint32_t a1 = Qs[abase + 8 * QS_S];
            uint32_t a2 = Qs[abase + 4];
            uint32_t a3 = Qs[abase + 8 * QS_S + 4];
            #pragma unroll
            for (int nt = 0; nt < 8; nt++) {
                uint32_t b0 = Ks[(nt * 8 + g) * KS_S + ks * 8 + tg];
                uint32_t b1 = Ks[(nt * 8 + g) * KS_S + ks * 8 + tg + 4];
                asm volatile(
                    "mma.sync.aligned.m16n8k8.row.col.f32.tf32.tf32.f32 "
                    "{%0,%1,%2,%3}, {%4,%5,%6,%7}, {%8,%9}, {%0,%1,%2,%3};"
                    : "+f"(sacc[nt][0]), "+f"(sacc[nt][1]),
                      "+f"(sacc[nt][2]), "+f"(sacc[nt][3])
                    : "r"(a0), "r"(a1), "r"(a2), "r"(a3), "r"(b0), "r"(b1));
            }
        }

        // ---- causal mask (diag tile only) ----
        if (jt == jmax) {
            #pragma unroll
            for (int nt = 0; nt < 8; nt++) {
                const int c0 = (jt << 6) + nt * 8 + 2 * tg;
                if (c0 > row0)     sacc[nt][0] = -1e30f;
                if (c0 + 1 > row0) sacc[nt][1] = -1e30f;
                if (c0 > row1)     sacc[nt][2] = -1e30f;
                if (c0 + 1 > row1) sacc[nt][3] = -1e30f;
            }
        }

        // ---- online softmax (rows g and g+8 of this warp's m16) ----
        float tm0 = -1e30f, tm1 = -1e30f;
        #pragma unroll
        for (int nt = 0; nt < 8; nt++) {
            tm0 = fmaxf(tm0, fmaxf(sacc[nt][0], sacc[nt][1]));
            tm1 = fmaxf(tm1, fmaxf(sacc[nt][2], sacc[nt][3]));
        }
        #pragma unroll
        for (int off = 1; off <= 2; off <<= 1) {
            tm0 = fmaxf(tm0, __shfl_xor_sync(0xffffffffu, tm0, off));
            tm1 = fmaxf(tm1, __shfl_xor_sync(0xffffffffu, tm1, off));
        }
        const float nm0 = fmaxf(m0, tm0), nm1 = fmaxf(m1, tm1);
        const float al0 = __expf(m0 - nm0), al1 = __expf(m1 - nm1);
        m0 = nm0; m1 = nm1;
        float ts0 = 0.0f, ts1 = 0.0f;
        #pragma unroll
        for (int nt = 0; nt < 8; nt++) {
            float p0 = __expf(sacc[nt][0] - nm0);
            float p1 = __expf(sacc[nt][1] - nm0);
            float p2 = __expf(sacc[nt][2] - nm1);
            float p3 = __expf(sacc[nt][3] - nm1);
            ts0 += p0 + p1; ts1 += p2 + p3;
            // store P (tf32) to smem in C-layout positions
            const int pb0 = (w * 16 + g) * PS_S + nt * 8 + 2 * tg;
            uint2 u01 = { f2tf(p0), f2tf(p1) };
            *reinterpret_cast<uint2*>(&Ps[pb0]) = u01;
            uint2 u23 = { f2tf(p2), f2tf(p3) };
            *reinterpret_cast<uint2*>(&Ps[pb0 + 8 * PS_S]) = u23;
        }
        #pragma unroll
        for (int off = 1; off <= 2; off <<= 1) {
            ts0 += __shfl_xor_sync(0xffffffffu, ts0, off);
            ts1 += __shfl_xor_sync(0xffffffffu, ts1, off);
        }
        l0 = l0 * al0 + ts0;
        l1 = l1 * al1 + ts1;
        #pragma unroll
        for (int nt = 0; nt < 8; nt++) {
            oacc[nt][0] *= al0; oacc[nt][1] *= al0;
            oacc[nt][2] *= al1; oacc[nt][3] *= al1;
        }
        __syncthreads();

        // ---- O += P (16x64) @ V (64x64) ----
        #pragma unroll
        for (int ks = 0; ks < 8; ks++) {
            const int abase = (w * 16 + g) * PS_S + ks * 8 + tg;
            uint32_t a0 = Ps[abase];
            uint32_t a1 = Ps[abase + 8 * PS_S];
            uint32_t a2 = Ps[abase + 4];
            uint32_t a3 = Ps[abase + 8 * PS_S + 4];
            #pragma unroll
            for (int nt = 0; nt < 8; nt++) {
                uint32_t b0 = Vs[(ks * 8 + tg) * VS_S + nt * 8 + g];
                uint32_t b1 = Vs[(ks * 8 + tg + 4) * VS_S + nt * 8 + g];
                asm volatile(
                    "mma.sync.aligned.m16n8k8.row.col.f32.tf32.tf32.f32 "
                    "{%0,%1,%2,%3}, {%4,%5,%6,%7}, {%8,%9}, {%0,%1,%2,%3};"
                    : "+f"(oacc[nt][0]), "+f"(oacc[nt][1]),
                      "+f"(oacc[nt][2]), "+f"(oacc[nt][3])
                    : "r"(a0), "r"(a1), "r"(a2), "r"(a3), "r"(b0), "r"(b1));
            }
        }
    }

    // ---- write O ----
    const float inv0 = 1.0f / l0, inv1 = 1.0f / l1;
    const size_t ob0 = (size_t)(b * TT + row0) * DD + h * 64;
    const size_t ob1 = (size_t)(b * TT + row1) * DD + h * 64;
    #pragma unroll
    for (int nt = 0; nt < 8; nt++) {
        const int col = nt * 8 + 2 * tg;
        float2 o0 = { oacc[nt][0] * inv0, oacc[nt][1] * inv0 };
        *reinterpret_cast<float2*>(O + ob0 + col) = o0;
        float2 o1 = { oacc[nt][2] * inv1, oacc[nt][3] * inv1 };
        *reinterpret_cast<float2*>(O + ob1 + col) = o1;
    }
}

// ===================== launch =====================
extern "C" void kernel_launch(void* const* d_in, const int* in_sizes, int n_in,
                              void* d_out, int out_size) {
    (void)in_sizes; (void)n_in; (void)out_size;
    const float* x   = (const float*)d_in[0];
    const float* g1  = (const float*)d_in[1];
    const float* bt1 = (const float*)d_in[2];
    const float* wq  = (const float*)d_in[3];
    const float* bq  = (const float*)d_in[4];
    const float* wk  = (const float*)d_in[5];
    const float* bk  = (const float*)d_in[6];
    const float* wv  = (const float*)d_in[7];
    const float* bv  = (const float*)d_in[8];
    const float* wo  = (const float*)d_in[9];
    const float* bo  = (const float*)d_in[10];
    const float* g2  = (const float*)d_in[11];
    const float* bt2 = (const float*)d_in[12];
    const float* w1  = (const float*)d_in[13];
    const float* b1  = (const float*)d_in[14];
    const float* w2  = (const float*)d_in[15];
    const float* b2  = (const float*)d_in[16];
    float* out = (float*)d_out;

    float *h1, *q, *k, *v, *ao, *x1, *h2, *f1;
    cudaGetSymbolAddress((void**)&h1, g_h1);
    cudaGetSymbolAddress((void**)&q,  g_q);
    cudaGetSymbolAddress((void**)&k,  g_k);
    cudaGetSymbolAddress((void**)&v,  g_v);
    cudaGetSymbolAddress((void**)&ao, g_ao);
    cudaGetSymbolAddress((void**)&x1, g_x1);
    cudaGetSymbolAddress((void**)&h2, g_h2);
    cudaGetSymbolAddress((void**)&f1, g_f1);

    const int ATTN_SMEM = ATTN_WORDS * (int)sizeof(uint32_t);
    cudaFuncSetAttribute(attn_mma, cudaFuncAttributeMaxDynamicSharedMemorySize, ATTN_SMEM);

    // 1. h1 = LN(x)
    ln_kernel<<<RR, 256>>>(x, g1, bt1, h1);
    // 2. fused q/k/v projections
    gemm_qkv<<<dim3(12, RR / 128), 256>>>(h1, wq, bq, wk, bk, wv, bv, q, k, v);
    // 3. attention (tf32 tensor cores)
    attn_mma<<<dim3(TT / 64, 16, BB), 128, ATTN_SMEM>>>(q, k, v, ao);
    // 4. x1 = x + ao @ wo + bo
    gemm_tf32<2><<<dim3(DD / 128, RR / 128), 256>>>(ao, wo, bo, x, x1, RR, DD, DD);
    // 5. h2 = LN(x1)
    ln_kernel<<<RR, 256>>>(x1, g2, bt2, h2);
    // 6. f1 = gelu(h2 @ w1 + b1)
    gemm_tf32<1><<<dim3(4 * DD / 128, RR / 128), 256>>>(h2, w1, b1, nullptr, f1, RR, 4 * DD, DD);
    // 7. out = x1 + f1 @ w2 + b2
    gemm_tf32<2><<<dim3(DD / 128, RR / 128), 256>>>(f1, w2, b2, x1, out, RR, DD, 4 * DD);
}

// round 4
// speedup vs baseline: 6.1445x; 1.8345x over previous
#include <cuda_runtime.h>
#include <cuda_fp16.h>
#include <math.h>
#include <stdint.h>

#define BB 2
#define TT 2048
#define DD 1024
#define RR (BB*TT)   // 4096 rows

// -------- scratch (device globals; no runtime allocation) --------
__device__ float g_h1[RR*DD];
__device__ float g_q [RR*DD];
__device__ float g_k [RR*256];
__device__ float g_v [RR*256];
__device__ float g_ao[RR*DD];
__device__ float g_x1[RR*DD];
__device__ float g_h2[RR*DD];
__device__ float g_f1[RR*4*DD];

__device__ __forceinline__ uint32_t smaddr(const void* p) {
    return (uint32_t)__cvta_generic_to_shared(p);
}
__device__ __forceinline__ void ldsm_x4(uint32_t& r0, uint32_t& r1, uint32_t& r2, uint32_t& r3, uint32_t a) {
    asm volatile("ldmatrix.sync.aligned.m8n8.x4.shared.b16 {%0,%1,%2,%3}, [%4];"
                 : "=r"(r0), "=r"(r1), "=r"(r2), "=r"(r3) : "r"(a));
}
__device__ __forceinline__ void ldsm_x2(uint32_t& r0, uint32_t& r1, uint32_t a) {
    asm volatile("ldmatrix.sync.aligned.m8n8.x2.shared.b16 {%0,%1}, [%2];"
                 : "=r"(r0), "=r"(r1) : "r"(a));
}
__device__ __forceinline__ void ldsm_x2t(uint32_t& r0, uint32_t& r1, uint32_t a) {
    asm volatile("ldmatrix.sync.aligned.m8n8.x2.trans.shared.b16 {%0,%1}, [%2];"
                 : "=r"(r0), "=r"(r1) : "r"(a));
}
#define MMA16(c, a0,a1,a2,a3, b0,b1) \
    asm volatile("mma.sync.aligned.m16n8k16.row.col.f32.f16.f16.f32 " \
                 "{%0,%1,%2,%3}, {%4,%5,%6,%7}, {%8,%9}, {%0,%1,%2,%3};" \
                 : "+f"((c)[0]), "+f"((c)[1]), "+f"((c)[2]), "+f"((c)[3]) \
                 : "r"(a0), "r"(a1), "r"(a2), "r"(a3), "r"(b0), "r"(b1))

__device__ __forceinline__ uint32_t h2pack(float x, float y) {
    __half2 h = __floats2half2_rn(x, y);
    return *reinterpret_cast<uint32_t*>(&h);
}

// ===================== LayerNorm =====================
__device__ __forceinline__ float block_sum256(float v, float* sh) {
    #pragma unroll
    for (int o = 16; o; o >>= 1) v += __shfl_xor_sync(0xffffffffu, v, o);
    if ((threadIdx.x & 31) == 0) sh[threadIdx.x >> 5] = v;
    __syncthreads();
    float t = sh[threadIdx.x & 7];
    #pragma unroll
    for (int o = 4; o; o >>= 1) t += __shfl_xor_sync(0xffffffffu, t, o);
    __syncthreads();
    return t;
}

__global__ void ln_kernel(const float* __restrict__ x, const float* __restrict__ gw,
                          const float* __restrict__ bw, float* __restrict__ out) {
    __shared__ float sh[8];
    const int row = blockIdx.x;
    const float4* xr = reinterpret_cast<const float4*>(x + (size_t)row * DD);
    float4 v = xr[threadIdx.x];
    float s = v.x + v.y + v.z + v.w;
    float tot = block_sum256(s, sh);
    float mean = tot * (1.0f / DD);
    float dx = v.x - mean, dy = v.y - mean, dz = v.z - mean, dw = v.w - mean;
    float s2 = dx*dx + dy*dy + dz*dz + dw*dw;
    float tot2 = block_sum256(s2, sh);
    float rstd = rsqrtf(tot2 * (1.0f / DD) + 1e-5f);
    float4 g4 = reinterpret_cast<const float4*>(gw)[threadIdx.x];
    float4 b4 = reinterpret_cast<const float4*>(bw)[threadIdx.x];
    float4 o;
    o.x = g4.x * dx * rstd + b4.x;
    o.y = g4.y * dy * rstd + b4.y;
    o.z = g4.z * dz * rstd + b4.z;
    o.w = g4.w * dw * rstd + b4.w;
    reinterpret_cast<float4*>(out + (size_t)row * DD)[threadIdx.x] = o;
}

// ===================== FP16 tensor-core GEMM =====================
// 128x128 CTA tile, k-step 32, 8 warps (2x4), warp 64x32, mma.m16n8k16.
#define AST 40    // halves per A smem row (32 + 8 pad)
#define BST 136   // halves per B smem row (128 + 8 pad)

template<int EPI>
__device__ __forceinline__ void gemm_body_h(
    const float* __restrict__ A, const float* __restrict__ Bm,
    const float* __restrict__ bias, const float* __restrict__ res,
    float* __restrict__ C, int N, int K, int brow, int bcol,
    __half* As, __half* Bs) {

    const int tid  = threadIdx.x;
    const int lane = tid & 31, wid = tid >> 5;
    const int wm = wid & 1, wn = wid >> 1;
    const int g  = lane >> 2, tg = lane & 3;

    float acc[4][4][4];
    #pragma unroll
    for (int mt = 0; mt < 4; mt++)
        #pragma unroll
        for (int nt = 0; nt < 4; nt++)
            #pragma unroll
            for (int c = 0; c < 4; c++) acc[mt][nt][c] = 0.0f;

    float4 pa[4], pb[4];

    // prologue: tile 0 -> regs -> smem buf 0
    #pragma unroll
    for (int r = 0; r < 4; r++) {
        const int f = tid + (r << 8);
        pa[r] = *reinterpret_cast<const float4*>(A + (size_t)(brow + (f >> 3)) * K + ((f & 7) << 2));
        pb[r] = *reinterpret_cast<const float4*>(Bm + (size_t)(f >> 5) * N + bcol + ((f & 31) << 2));
    }
    #pragma unroll
    for (int r = 0; r < 4; r++) {
        const int f = tid + (r << 8);
        uint2 ua = { h2pack(pa[r].x, pa[r].y), h2pack(pa[r].z, pa[r].w) };
        *reinterpret_cast<uint2*>(&As[(f >> 3) * AST + ((f & 7) << 2)]) = ua;
        uint2 ub = { h2pack(pb[r].x, pb[r].y), h2pack(pb[r].z, pb[r].w) };
        *reinterpret_cast<uint2*>(&Bs[(f >> 5) * BST + ((f & 31) << 2)]) = ub;
    }
    __syncthreads();

    const int nk = K >> 5;
    const int l15 = lane & 15;
    for (int kt = 0; kt < nk; kt++) {
        const int cur = kt & 1;
        __half* Asc = As + cur * (128 * AST);
        __half* Bsc = Bs + cur * (32 * BST);
        if (kt + 1 < nk) {
            const int k0 = (kt + 1) << 5;
            #pragma unroll
            for (int r = 0; r < 4; r++) {
                const int f = tid + (r << 8);
                pa[r] = *reinterpret_cast<const float4*>(A + (size_t)(brow + (f >> 3)) * K + k0 + ((f & 7) << 2));
                pb[r] = *reinterpret_cast<const float4*>(Bm + (size_t)(k0 + (f >> 5)) * N + bcol + ((f & 31) << 2));
            }
        }
        #pragma unroll
        for (int ks = 0; ks < 2; ks++) {
            uint32_t af[4][4], bf[4][2];
            const int koff = ks * 16 + ((lane >> 4) << 3);
            #pragma unroll
            for (int mt = 0; mt < 4; mt++)
                ldsm_x4(af[mt][0], af[mt][1], af[mt][2], af[mt][3],
                        smaddr(&Asc[(wm * 64 + mt * 16 + l15) * AST + koff]));
            #pragma unroll
            for (int nt = 0; nt < 4; nt++)
                ldsm_x2t(bf[nt][0], bf[nt][1],
                         smaddr(&Bsc[(ks * 16 + l15) * BST + wn * 32 + nt * 8]));
            #pragma unroll
            for (int mt = 0; mt < 4; mt++)
                #pragma unroll
                for (int nt = 0; nt < 4; nt++)
                    MMA16(acc[mt][nt], af[mt][0], af[mt][1], af[mt][2], af[mt][3],
                          bf[nt][0], bf[nt][1]);
        }
        if (kt + 1 < nk) {
            __half* Asn = As + (cur ^ 1) * (128 * AST);
            __half* Bsn = Bs + (cur ^ 1) * (32 * BST);
            #pragma unroll
            for (int r = 0; r < 4; r++) {
                const int f = tid + (r << 8);
                uint2 ua = { h2pack(pa[r].x, pa[r].y), h2pack(pa[r].z, pa[r].w) };
                *reinterpret_cast<uint2*>(&Asn[(f >> 3) * AST + ((f & 7) << 2)]) = ua;
                uint2 ub = { h2pack(pb[r].x, pb[r].y), h2pack(pb[r].z, pb[r].w) };
                *reinterpret_cast<uint2*>(&Bsn[(f >> 5) * BST + ((f & 31) << 2)]) = ub;
            }
        }
        __syncthreads();
    }

    #pragma unroll
    for (int mt = 0; mt < 4; mt++) {
        #pragma unroll
        for (int half = 0; half < 2; half++) {
            const int row = brow + wm * 64 + mt * 16 + g + half * 8;
            float* Crow = C + (size_t)row * N;
            #pragma unroll
            for (int nt = 0; nt < 4; nt++) {
                const int col = bcol + wn * 32 + nt * 8 + tg * 2;
                float v0 = acc[mt][nt][half * 2 + 0] + bias[col];
                float v1 = acc[mt][nt][half * 2 + 1] + bias[col + 1];
                if (EPI == 1) {
                    v0 = 0.5f * v0 * (1.0f + erff(v0 * 0.70710678118654752f));
                    v1 = 0.5f * v1 * (1.0f + erff(v1 * 0.70710678118654752f));
                }
                if (EPI == 2) {
                    float2 rr = *reinterpret_cast<const float2*>(res + (size_t)row * N + col);
                    v0 += rr.x; v1 += rr.y;
                }
                float2 o2; o2.x = v0; o2.y = v1;
                *reinterpret_cast<float2*>(Crow + col) = o2;
            }
        }
    }
}

template<int EPI>
__global__ void __launch_bounds__(256, 2)
gemm_h(const float* __restrict__ A, const float* __restrict__ Bm,
       const float* __restrict__ bias, const float* __restrict__ res,
       float* __restrict__ C, int N, int K) {
    __shared__ __half As[2 * 128 * AST];
    __shared__ __half Bs[2 * 32 * BST];
    gemm_body_h<EPI>(A, Bm, bias, res, C, N, K, blockIdx.y * 128, blockIdx.x * 128, As, Bs);
}

// fused QKV: grid.x = 12 (8 q tiles, 2 k tiles, 2 v tiles)
__global__ void __launch_bounds__(256, 2)
gemm_qkv(const float* __restrict__ A,
         const float* __restrict__ wq, const float* __restrict__ bq,
         const float* __restrict__ wk, const float* __restrict__ bk,
         const float* __restrict__ wv, const float* __restrict__ bv,
         float* __restrict__ q, float* __restrict__ k, float* __restrict__ v) {
    __shared__ __half As[2 * 128 * AST];
    __shared__ __half Bs[2 * 32 * BST];
    const int bx = blockIdx.x;
    const float *Bm, *bias; float* C; int N, bcol;
    if (bx < 8)       { Bm = wq; bias = bq; C = q; N = 1024; bcol = bx * 128; }
    else if (bx < 10) { Bm = wk; bias = bk; C = k; N = 256;  bcol = (bx - 8) * 128; }
    else              { Bm = wv; bias = bv; C = v; N = 256;  bcol = (bx - 10) * 128; }
    gemm_body_h<0>(A, Bm, bias, nullptr, C, N, DD, blockIdx.y * 128, bcol, As, Bs);
}

// ===================== Flash attention (fp16 mma, causal, GQA) =====================
// grid (T/128, 16, B), 256 threads (8 warps, each owns 16 q rows)
#define QST 72
#define KST 72
#define VST 72
#define ATTN_HALVES (128*QST + 64*KST + 64*VST)

__global__ void __launch_bounds__(256, 2)
attn_h(const float* __restrict__ Q, const float* __restrict__ K,
       const float* __restrict__ V, float* __restrict__ O) {
    extern __shared__ __half smh[];
    __half* Qs = smh;
    __half* Ks = smh + 128 * QST;
    __half* Vs = Ks + 64 * KST;

    const int tid = threadIdx.x;
    const int lane = tid & 31, w = tid >> 5;
    const int g = lane >> 2, tg = lane & 3;
    const int l15 = lane & 15;
    const int h = blockIdx.y, b = blockIdx.z, grp = h >> 2;
    const int q0 = blockIdx.x << 7;

    // load Q tile (128 x 64), scaled by 1/8, fp16
    {
        const size_t qbase = (size_t)(b * TT + q0) * DD + h * 64;
        #pragma unroll
        for (int i = 0; i < 8; i++) {
            const int f = tid + (i << 8);
            const int r = f >> 4, c = (f & 15) << 2;
            float4 v4 = *reinterpret_cast<const float4*>(Q + qbase + (size_t)r * DD + c);
            uint2 u = { h2pack(v4.x * 0.125f, v4.y * 0.125f),
                        h2pack(v4.z * 0.125f, v4.w * 0.125f) };
            *reinterpret_cast<uint2*>(&Qs[r * QST + c]) = u;
        }
    }
    __syncthreads();

    // hoist Q fragments (invariant across KV tiles)
    uint32_t qf[4][4];
    {
        const int koff = (lane >> 4) << 3;
        #pragma unroll
        for (int ks = 0; ks < 4; ks++)
            ldsm_x4(qf[ks][0], qf[ks][1], qf[ks][2], qf[ks][3],
                    smaddr(&Qs[(w * 16 + l15) * QST + ks * 16 + koff]));
    }

    float oacc[8][4];
    #pragma unroll
    for (int nt = 0; nt < 8; nt++)
        #pragma unroll
        for (int c = 0; c < 4; c++) oacc[nt][c] = 0.0f;
    float m0 = -1e30f, m1 = -1e30f, l0 = 0.0f, l1 = 0.0f;

    const int roww = q0 + w * 16;        // warp's first q row
    const int row0 = roww + g, row1 = roww + g + 8;

    const int jmax = 2 * blockIdx.x + 1;
    for (int jt = 0; jt <= jmax; jt++) {
        __syncthreads();   // previous PV reads of Vs complete
        {
            const size_t kvbase = (size_t)(b * TT + (jt << 6)) * 256 + grp * 64;
            #pragma unroll
            for (int i = 0; i < 4; i++) {
                const int f = tid + (i << 8);
                const int r = f >> 4, c = (f & 15) << 2;
                float4 kk = *reinterpret_cast<const float4*>(K + kvbase + (size_t)r * 256 + c);
                uint2 uk = { h2pack(kk.x, kk.y), h2pack(kk.z, kk.w) };
                *reinterpret_cast<uint2*>(&Ks[r * KST + c]) = uk;
                float4 vv = *reinterpret_cast<const float4*>(V + kvbase + (size_t)r * 256 + c);
                uint2 uv = { h2pack(vv.x, vv.y), h2pack(vv.z, vv.w) };
                *reinterpret_cast<uint2*>(&Vs[r * VST + c]) = uv;
            }
        }
        __syncthreads();

        const int ktile0 = jt << 6;
        if (ktile0 <= roww + 15) {       // warp has unmasked work
            // ---- S = Q K^T ----
            float sacc[8][4];
            #pragma unroll
            for (int nt = 0; nt < 8; nt++)
                #pragma unroll
                for (int c = 0; c < 4; c++) sacc[nt][c] = 0.0f;
            #pragma unroll
            for (int ks = 0; ks < 4; ks++) {
                const int koff = ks * 16 + ((l15 >> 3) << 3);
                #pragma unroll
                for (int nt = 0; nt < 8; nt++) {
                    uint32_t b0, b1;
                    ldsm_x2(b0, b1, smaddr(&Ks[(nt * 8 + (l15 & 7)) * KST + koff]));
                    MMA16(sacc[nt], qf[ks][0], qf[ks][1], qf[ks][2], qf[ks][3], b0, b1);
                }
            }

            // ---- causal mask ----
            if (ktile0 + 63 > roww) {
                #pragma unroll
                for (int nt = 0; nt < 8; nt++) {
                    const int c0 = ktile0 + nt * 8 + 2 * tg;
                    if (c0 > row0)     sacc[nt][0] = -1e30f;
                    if (c0 + 1 > row0) sacc[nt][1] = -1e30f;
                    if (c0 > row1)     sacc[nt][2] = -1e30f;
                    if (c0 + 1 > row1) sacc[nt][3] = -1e30f;
                }
            }

            // ---- online softmax ----
            float tm0 = -1e30f, tm1 = -1e30f;
            #pragma unroll
            for (int nt = 0; nt < 8; nt++) {
                tm0 = fmaxf(tm0, fmaxf(sacc[nt][0], sacc[nt][1]));
                tm1 = fmaxf(tm1, fmaxf(sacc[nt][2], sacc[nt][3]));
            }
            #pragma unroll
            for (int off = 1; off <= 2; off <<= 1) {
                tm0 = fmaxf(tm0, __shfl_xor_sync(0xffffffffu, tm0, off));
                tm1 = fmaxf(tm1, __shfl_xor_sync(0xffffffffu, tm1, off));
            }
            const float nm0 = fmaxf(m0, tm0), nm1 = fmaxf(m1, tm1);
            const float al0 = __expf(m0 - nm0), al1 = __expf(m1 - nm1);
            m0 = nm0; m1 = nm1;
            float ts0 = 0.0f, ts1 = 0.0f;
            #pragma unroll
            for (int nt = 0; nt < 8; nt++) {
                sacc[nt][0] = __expf(sacc[nt][0] - nm0);
                sacc[nt][1] = __expf(sacc[nt][1] - nm0);
                sacc[nt][2] = __expf(sacc[nt][2] - nm1);
                sacc[nt][3] = __expf(sacc[nt][3] - nm1);
                ts0 += sacc[nt][0] + sacc[nt][1];
                ts1 += sacc[nt][2] + sacc[nt][3];
            }
            #pragma unroll
            for (int off = 1; off <= 2; off <<= 1) {
                ts0 += __shfl_xor_sync(0xffffffffu, ts0, off);
                ts1 += __shfl_xor_sync(0xffffffffu, ts1, off);
            }
            l0 = l0 * al0 + ts0;
            l1 = l1 * al1 + ts1;
            #pragma unroll
            for (int nt = 0; nt < 8; nt++) {
                oacc[nt][0] *= al0; oacc[nt][1] *= al0;
                oacc[nt][2] *= al1; oacc[nt][3] *= al1;
            }

            // ---- O += P @ V  (P repacked in registers, no smem) ----
            #pragma unroll
            for (int ks = 0; ks < 4; ks++) {
                const uint32_t a0 = h2pack(sacc[2*ks][0],   sacc[2*ks][1]);
                const uint32_t a1 = h2pack(sacc[2*ks][2],   sacc[2*ks][3]);
                const uint32_t a2 = h2pack(sacc[2*ks+1][0], sacc[2*ks+1][1]);
                const uint32_t a3 = h2pack(sacc[2*ks+1][2], sacc[2*ks+1][3]);
                #pragma unroll
                for (int nt = 0; nt < 8; nt++) {
                    uint32_t b0, b1;
                    ldsm_x2t(b0, b1, smaddr(&Vs[(ks * 16 + l15) * VST + nt * 8]));
                    MMA16(oacc[nt], a0, a1, a2, a3, b0, b1);
                }
            }
        }
    }

    // ---- write O ----
    const float inv0 = 1.0f / l0, inv1 = 1.0f / l1;
    const size_t ob0 = (size_t)(b * TT + row0) * DD + h * 64;
    const size_t ob1 = (size_t)(b * TT + row1) * DD + h * 64;
    #pragma unroll
    for (int nt = 0; nt < 8; nt++) {
        const int col = nt * 8 + 2 * tg;
        float2 o0 = { oacc[nt][0] * inv0, oacc[nt][1] * inv0 };
        *reinterpret_cast<float2*>(O + ob0 + col) = o0;
        float2 o1 = { oacc[nt][2] * inv1, oacc[nt][3] * inv1 };
        *reinterpret_cast<float2*>(O + ob1 + col) = o1;
    }
}

// ===================== launch =====================
extern "C" void kernel_launch(void* const* d_in, const int* in_sizes, int n_in,
                              void* d_out, int out_size) {
    (void)in_sizes; (void)n_in; (void)out_size;
    const float* x   = (const float*)d_in[0];
    const float* g1  = (const float*)d_in[1];
    const float* bt1 = (const float*)d_in[2];
    const float* wq  = (const float*)d_in[3];
    const float* bq  = (const float*)d_in[4];
    const float* wk  = (const float*)d_in[5];
    const float* bk  = (const float*)d_in[6];
    const float* wv  = (const float*)d_in[7];
    const float* bv  = (const float*)d_in[8];
    const float* wo  = (const float*)d_in[9];
    const float* bo  = (const float*)d_in[10];
    const float* g2  = (const float*)d_in[11];
    const float* bt2 = (const float*)d_in[12];
    const float* w1  = (const float*)d_in[13];
    const float* b1  = (const float*)d_in[14];
    const float* w2  = (const float*)d_in[15];
    const float* b2  = (const float*)d_in[16];
    float* out = (float*)d_out;

    float *h1, *q, *k, *v, *ao, *x1, *h2, *f1;
    cudaGetSymbolAddress((void**)&h1, g_h1);
    cudaGetSymbolAddress((void**)&q,  g_q);
    cudaGetSymbolAddress((void**)&k,  g_k);
    cudaGetSymbolAddress((void**)&v,  g_v);
    cudaGetSymbolAddress((void**)&ao, g_ao);
    cudaGetSymbolAddress((void**)&x1, g_x1);
    cudaGetSymbolAddress((void**)&h2, g_h2);
    cudaGetSymbolAddress((void**)&f1, g_f1);

    const int ATTN_SMEM = ATTN_HALVES * (int)sizeof(__half);
    cudaFuncSetAttribute(attn_h, cudaFuncAttributeMaxDynamicSharedMemorySize, ATTN_SMEM);

    // 1. h1 = LN(x)
    ln_kernel<<<RR, 256>>>(x, g1, bt1, h1);
    // 2. fused q/k/v projections
    gemm_qkv<<<dim3(12, RR / 128), 256>>>(h1, wq, bq, wk, bk, wv, bv, q, k, v);
    // 3. attention
    attn_h<<<dim3(TT / 128, 16, BB), 256, ATTN_SMEM>>>(q, k, v, ao);
    // 4. x1 = x + ao @ wo + bo
    gemm_h<2><<<dim3(DD / 128, RR / 128), 256>>>(ao, wo, bo, x, x1, DD, DD);
    // 5. h2 = LN(x1)
    ln_kernel<<<RR, 256>>>(x1, g2, bt2, h2);
    // 6. f1 = gelu(h2 @ w1 + b1)
    gemm_h<1><<<dim3(4 * DD / 128, RR / 128), 256>>>(h2, w1, b1, nullptr, f1, 4 * DD, DD);
    // 7. out = x1 + f1 @ w2 + b2
    gemm_h<2><<<dim3(DD / 128, RR / 128), 256>>>(f1, w2, b2, x1, out, DD, 4 * DD);
}

// round 5
// speedup vs baseline: 7.1154x; 1.1580x over previous
#include <cuda_runtime.h>
#include <cuda_fp16.h>
#include <math.h>
#include <stdint.h>

#define BB 2
#define TT 2048
#define DD 1024
#define RR (BB*TT)   // 4096 rows

// -------- scratch (device globals; no runtime allocation) --------
__device__ __half g_h1[RR*DD];
__device__ __half g_q [RR*DD];
__device__ __half g_k [RR*256];
__device__ __half g_v [RR*256];
__device__ __half g_ao[RR*DD];
__device__ float  g_x1[RR*DD];
__device__ __half g_h2[RR*DD];
__device__ __half g_f1[RR*4*DD];
// fp16 weights
__device__ __half g_wq[DD*DD];
__device__ __half g_wk[DD*256];
__device__ __half g_wv[DD*256];
__device__ __half g_wo[DD*DD];
__device__ __half g_w1[DD*4*DD];
__device__ __half g_w2[4*DD*DD];

__device__ __forceinline__ uint32_t smaddr(const void* p) {
    return (uint32_t)__cvta_generic_to_shared(p);
}
__device__ __forceinline__ void cp16(uint32_t dst, const void* src) {
    asm volatile("cp.async.cg.shared.global [%0], [%1], 16;" :: "r"(dst), "l"(src));
}
#define CP_COMMIT() asm volatile("cp.async.commit_group;" ::: "memory")
#define CP_WAIT0()  asm volatile("cp.async.wait_group 0;" ::: "memory")

__device__ __forceinline__ void ldsm_x4(uint32_t& r0, uint32_t& r1, uint32_t& r2, uint32_t& r3, uint32_t a) {
    asm volatile("ldmatrix.sync.aligned.m8n8.x4.shared.b16 {%0,%1,%2,%3}, [%4];"
                 : "=r"(r0), "=r"(r1), "=r"(r2), "=r"(r3) : "r"(a));
}
__device__ __forceinline__ void ldsm_x2(uint32_t& r0, uint32_t& r1, uint32_t a) {
    asm volatile("ldmatrix.sync.aligned.m8n8.x2.shared.b16 {%0,%1}, [%2];"
                 : "=r"(r0), "=r"(r1) : "r"(a));
}
__device__ __forceinline__ void ldsm_x2t(uint32_t& r0, uint32_t& r1, uint32_t a) {
    asm volatile("ldmatrix.sync.aligned.m8n8.x2.trans.shared.b16 {%0,%1}, [%2];"
                 : "=r"(r0), "=r"(r1) : "r"(a));
}
#define MMA16(c, a0,a1,a2,a3, b0,b1) \
    asm volatile("mma.sync.aligned.m16n8k16.row.col.f32.f16.f16.f32 " \
                 "{%0,%1,%2,%3}, {%4,%5,%6,%7}, {%8,%9}, {%0,%1,%2,%3};" \
                 : "+f"((c)[0]), "+f"((c)[1]), "+f"((c)[2]), "+f"((c)[3]) \
                 : "r"(a0), "r"(a1), "r"(a2), "r"(a3), "r"(b0), "r"(b1))

__device__ __forceinline__ uint32_t h2pack(float x, float y) {
    __half2 h = __floats2half2_rn(x, y);
    return *reinterpret_cast<uint32_t*>(&h);
}

// ===================== weight conversion (fp32 -> fp16) =====================
#define C0 262144     // wq  (1M elts / 4)
#define C1 327680     // +wk (256K/4)
#define C2 393216     // +wv
#define C3 655360     // +wo
#define C4 1703936    // +w1 (4M/4)
#define C5 2752512    // +w2
__global__ void cvt_w(const float* __restrict__ s0, const float* __restrict__ s1,
                      const float* __restrict__ s2, const float* __restrict__ s3,
                      const float* __restrict__ s4, const float* __restrict__ s5,
                      __half* d0, __half* d1, __half* d2,
                      __half* d3, __half* d4, __half* d5) {
    const int i = blockIdx.x * blockDim.x + threadIdx.x;
    if (i >= C5) return;
    const float* s; __half* d; int base;
    if      (i < C0) { s = s0; d = d0; base = 0;  }
    else if (i < C1) { s = s1; d = d1; base = C0; }
    else if (i < C2) { s = s2; d = d2; base = C1; }
    else if (i < C3) { s = s3; d = d3; base = C2; }
    else if (i < C4) { s = s4; d = d4; base = C3; }
    else             { s = s5; d = d5; base = C4; }
    const int j = i - base;
    float4 v = reinterpret_cast<const float4*>(s)[j];
    uint2 u = { h2pack(v.x, v.y), h2pack(v.z, v.w) };
    reinterpret_cast<uint2*>(d)[j] = u;
}

// ===================== LayerNorm (fp32 in, fp16 out) =====================
__device__ __forceinline__ float block_sum256(float v, float* sh) {
    #pragma unroll
    for (int o = 16; o; o >>= 1) v += __shfl_xor_sync(0xffffffffu, v, o);
    if ((threadIdx.x & 31) == 0) sh[threadIdx.x >> 5] = v;
    __syncthreads();
    float t = sh[threadIdx.x & 7];
    #pragma unroll
    for (int o = 4; o; o >>= 1) t += __shfl_xor_sync(0xffffffffu, t, o);
    __syncthreads();
    return t;
}

__global__ void ln_kernel(const float* __restrict__ x, const float* __restrict__ gw,
                          const float* __restrict__ bw, __half* __restrict__ out) {
    __shared__ float sh[8];
    const int row = blockIdx.x;
    const float4* xr = reinterpret_cast<const float4*>(x + (size_t)row * DD);
    float4 v = xr[threadIdx.x];
    float s = v.x + v.y + v.z + v.w;
    float tot = block_sum256(s, sh);
    float mean = tot * (1.0f / DD);
    float dx = v.x - mean, dy = v.y - mean, dz = v.z - mean, dw = v.w - mean;
    float s2 = dx*dx + dy*dy + dz*dz + dw*dw;
    float tot2 = block_sum256(s2, sh);
    float rstd = rsqrtf(tot2 * (1.0f / DD) + 1e-5f);
    float4 g4 = reinterpret_cast<const float4*>(gw)[threadIdx.x];
    float4 b4 = reinterpret_cast<const float4*>(bw)[threadIdx.x];
    uint2 o = { h2pack(g4.x * dx * rstd + b4.x, g4.y * dy * rstd + b4.y),
                h2pack(g4.z * dz * rstd + b4.z, g4.w * dw * rstd + b4.w) };
    reinterpret_cast<uint2*>(out + (size_t)row * DD)[threadIdx.x] = o;
}

// ===================== FP16 tensor-core GEMM (cp.async) =====================
// 128x128 CTA tile, k-step 32, 8 warps (2x4), warp 64x32, mma.m16n8k16.
#define AST 40    // halves per A smem row (80B = 5x16B, conflict-free phases)
#define BST 136   // halves per B smem row (272B = 17x16B)

// EPI: 0 none, 1 GELU, 2 +=res ; OUTH: output half (else float)
template<int EPI, bool OUTH>
__device__ __forceinline__ void gemm_body_h(
    const __half* __restrict__ A, const __half* __restrict__ Bm,
    const float* __restrict__ bias, const float* __restrict__ res,
    void* __restrict__ C, int N, int K, int brow, int bcol,
    __half* As, __half* Bs, float oscale) {

    const int tid  = threadIdx.x;
    const int lane = tid & 31, wid = tid >> 5;
    const int wm = wid & 1, wn = wid >> 1;
    const int g  = lane >> 2, tg = lane & 3;
    const int l15 = lane & 15;

    float acc[4][4][4];
    #pragma unroll
    for (int mt = 0; mt < 4; mt++)
        #pragma unroll
        for (int nt = 0; nt < 4; nt++)
            #pragma unroll
            for (int c = 0; c < 4; c++) acc[mt][nt][c] = 0.0f;

    // per-thread copy coords
    const int ar = tid >> 1, ac = (tid & 1) << 4;          // A: 128 rows x 2 chunks(16h)
    const int br = tid >> 4, bc = (tid & 15) << 3;         // B: 16 rows x 16 chunks... (32 rows, 2 passes)
    // A tile: 128x32 halves = 256 chunks of 16 halves? No: 16B=8 halves; A row=32h=4 chunks -> 512 chunks.
    // Use: f = tid + r*256 (r=0..1): row=f>>2, col=(f&3)*8
    // B tile: 32x128h, row chunks=16 -> 512 chunks: row=f>>4, col=(f&15)*8
    (void)ar; (void)ac; (void)br; (void)bc;

    // prologue: tile 0
    #pragma unroll
    for (int r = 0; r < 2; r++) {
        const int f = tid + (r << 8);
        cp16(smaddr(&As[(f >> 2) * AST + ((f & 3) << 3)]),
             A + (size_t)(brow + (f >> 2)) * K + ((f & 3) << 3));
        cp16(smaddr(&Bs[(f >> 4) * BST + ((f & 15) << 3)]),
             Bm + (size_t)(f >> 4) * N + bcol + ((f & 15) << 3));
    }
    CP_COMMIT();
    CP_WAIT0();
    __syncthreads();

    const int nk = K >> 5;
    for (int kt = 0; kt < nk; kt++) {
        const int cur = kt & 1;
        __half* Asc = As + cur * (128 * AST);
        __half* Bsc = Bs + cur * (32 * BST);
        if (kt + 1 < nk) {
            const int k0 = (kt + 1) << 5;
            __half* Asn = As + (cur ^ 1) * (128 * AST);
            __half* Bsn = Bs + (cur ^ 1) * (32 * BST);
            #pragma unroll
            for (int r = 0; r < 2; r++) {
                const int f = tid + (r << 8);
                cp16(smaddr(&Asn[(f >> 2) * AST + ((f & 3) << 3)]),
                     A + (size_t)(brow + (f >> 2)) * K + k0 + ((f & 3) << 3));
                cp16(smaddr(&Bsn[(f >> 4) * BST + ((f & 15) << 3)]),
                     Bm + (size_t)(k0 + (f >> 4)) * N + bcol + ((f & 15) << 3));
            }
            CP_COMMIT();
        }
        #pragma unroll
        for (int ks = 0; ks < 2; ks++) {
            uint32_t af[4][4], bf[4][2];
            const int koff = ks * 16 + ((lane >> 4) << 3);
            #pragma unroll
            for (int mt = 0; mt < 4; mt++)
                ldsm_x4(af[mt][0], af[mt][1], af[mt][2], af[mt][3],
                        smaddr(&Asc[(wm * 64 + mt * 16 + l15) * AST + koff]));
            #pragma unroll
            for (int nt = 0; nt < 4; nt++)
                ldsm_x2t(bf[nt][0], bf[nt][1],
                         smaddr(&Bsc[(ks * 16 + l15) * BST + wn * 32 + nt * 8]));
            #pragma unroll
            for (int mt = 0; mt < 4; mt++)
                #pragma unroll
                for (int nt = 0; nt < 4; nt++)
                    MMA16(acc[mt][nt], af[mt][0], af[mt][1], af[mt][2], af[mt][3],
                          bf[nt][0], bf[nt][1]);
        }
        if (kt + 1 < nk) CP_WAIT0();
        __syncthreads();
    }

    #pragma unroll
    for (int mt = 0; mt < 4; mt++) {
        #pragma unroll
        for (int half = 0; half < 2; half++) {
            const int row = brow + wm * 64 + mt * 16 + g + half * 8;
            #pragma unroll
            for (int nt = 0; nt < 4; nt++) {
                const int col = bcol + wn * 32 + nt * 8 + tg * 2;
                float v0 = acc[mt][nt][half * 2 + 0] + bias[col];
                float v1 = acc[mt][nt][half * 2 + 1] + bias[col + 1];
                if (EPI == 1) {
                    v0 = 0.5f * v0 * (1.0f + erff(v0 * 0.70710678118654752f));
                    v1 = 0.5f * v1 * (1.0f + erff(v1 * 0.70710678118654752f));
                }
                if (EPI == 2) {
                    float2 rr = *reinterpret_cast<const float2*>(res + (size_t)row * N + col);
                    v0 += rr.x; v1 += rr.y;
                }
                v0 *= oscale; v1 *= oscale;
                if (OUTH) {
                    *reinterpret_cast<uint32_t*>((__half*)C + (size_t)row * N + col) = h2pack(v0, v1);
                } else {
                    float2 o2; o2.x = v0; o2.y = v1;
                    *reinterpret_cast<float2*>((float*)C + (size_t)row * N + col) = o2;
                }
            }
        }
    }
}

template<int EPI, bool OUTH>
__global__ void __launch_bounds__(256, 2)
gemm_h(const __half* __restrict__ A, const __half* __restrict__ Bm,
       const float* __restrict__ bias, const float* __restrict__ res,
       void* __restrict__ C, int N, int K) {
    __shared__ __half As[2 * 128 * AST];
    __shared__ __half Bs[2 * 32 * BST];
    gemm_body_h<EPI, OUTH>(A, Bm, bias, res, C, N, K, blockIdx.y * 128, blockIdx.x * 128, As, Bs, 1.0f);
}

// fused QKV: grid.x = 12 (8 q tiles, 2 k tiles, 2 v tiles); Q pre-scaled by 0.125
__global__ void __launch_bounds__(256, 2)
gemm_qkv(const __half* __restrict__ A,
         const __half* __restrict__ wq, const float* __restrict__ bq,
         const __half* __restrict__ wk, const float* __restrict__ bk,
         const __half* __restrict__ wv, const float* __restrict__ bv,
         __half* __restrict__ q, __half* __restrict__ k, __half* __restrict__ v) {
    __shared__ __half As[2 * 128 * AST];
    __shared__ __half Bs[2 * 32 * BST];
    const int bx = blockIdx.x;
    const __half* Bm; const float* bias; __half* C; int N, bcol; float sc;
    if (bx < 8)       { Bm = wq; bias = bq; C = q; N = 1024; bcol = bx * 128;        sc = 0.125f; }
    else if (bx < 10) { Bm = wk; bias = bk; C = k; N = 256;  bcol = (bx - 8) * 128;  sc = 1.0f; }
    else              { Bm = wv; bias = bv; C = v; N = 256;  bcol = (bx - 10) * 128; sc = 1.0f; }
    gemm_body_h<0, true>(A, Bm, bias, nullptr, C, N, DD, blockIdx.y * 128, bcol, As, Bs, sc);
}

// ===================== Flash attention (fp16 mma, causal, GQA) =====================
// grid (T/128, 16, B), 256 threads (8 warps, each owns 16 q rows)
// K/V double-buffered, cp.async loads.
#define QST 72
#define KST 72
#define VST 72
#define ATTN_HALVES (128*QST + 2*64*KST + 2*64*VST)

__global__ void __launch_bounds__(256, 2)
attn_h(const __half* __restrict__ Q, const __half* __restrict__ K,
       const __half* __restrict__ V, __half* __restrict__ O) {
    extern __shared__ __half smh[];
    __half* Qs = smh;
    __half* Ks = smh + 128 * QST;        // 2 bufs of 64*KST
    __half* Vs = Ks + 2 * 64 * KST;      // 2 bufs of 64*VST

    const int tid = threadIdx.x;
    const int lane = tid & 31, w = tid >> 5;
    const int g = lane >> 2, tg = lane & 3;
    const int l15 = lane & 15;
    const int h = blockIdx.y, b = blockIdx.z, grp = h >> 2;
    const int q0 = blockIdx.x << 7;

    // Q tile (128x64h): 1024 chunks of 8h
    {
        const size_t qbase = (size_t)(b * TT + q0) * DD + h * 64;
        #pragma unroll
        for (int i = 0; i < 4; i++) {
            const int f = tid + (i << 8);
            const int r = f >> 3, c = (f & 7) << 3;
            cp16(smaddr(&Qs[r * QST + c]), Q + qbase + (size_t)r * DD + c);
        }
    }
    // K/V tile 0: 512 chunks each
    {
        const size_t kvbase = (size_t)(b * TT) * 256 + grp * 64;
        #pragma unroll
        for (int i = 0; i < 2; i++) {
            const int f = tid + (i << 8);
            const int r = f >> 3, c = (f & 7) << 3;
            cp16(smaddr(&Ks[r * KST + c]), K + kvbase + (size_t)r * 256 + c);
            cp16(smaddr(&Vs[r * VST + c]), V + kvbase + (size_t)r * 256 + c);
        }
    }
    CP_COMMIT();
    CP_WAIT0();
    __syncthreads();

    // hoist Q fragments
    uint32_t qf[4][4];
    {
        const int koff = (lane >> 4) << 3;
        #pragma unroll
        for (int ks = 0; ks < 4; ks++)
            ldsm_x4(qf[ks][0], qf[ks][1], qf[ks][2], qf[ks][3],
                    smaddr(&Qs[(w * 16 + l15) * QST + ks * 16 + koff]));
    }

    float oacc[8][4];
    #pragma unroll
    for (int nt = 0; nt < 8; nt++)
        #pragma unroll
        for (int c = 0; c < 4; c++) oacc[nt][c] = 0.0f;
    float m0 = -1e30f, m1 = -1e30f, l0 = 0.0f, l1 = 0.0f;

    const int roww = q0 + w * 16;
    const int row0 = roww + g, row1 = roww + g + 8;

    const int jmax = 2 * blockIdx.x + 1;
    for (int jt = 0; jt <= jmax; jt++) {
        const int cur = jt & 1;
        __half* Ksc = Ks + cur * (64 * KST);
        __half* Vsc = Vs + cur * (64 * VST);
        if (jt + 1 <= jmax) {
            __half* Ksn = Ks + (cur ^ 1) * (64 * KST);
            __half* Vsn = Vs + (cur ^ 1) * (64 * VST);
            const size_t kvbase = (size_t)(b * TT + ((jt + 1) << 6)) * 256 + grp * 64;
            #pragma unroll
            for (int i = 0; i < 2; i++) {
                const int f = tid + (i << 8);
                const int r = f >> 3, c = (f & 7) << 3;
                cp16(smaddr(&Ksn[r * KST + c]), K + kvbase + (size_t)r * 256 + c);
                cp16(smaddr(&Vsn[r * VST + c]), V + kvbase + (size_t)r * 256 + c);
            }
            CP_COMMIT();
        }

        const int ktile0 = jt << 6;
        if (ktile0 <= roww + 15) {
            // ---- S = Q K^T ----
            float sacc[8][4];
            #pragma unroll
            for (int nt = 0; nt < 8; nt++)
                #pragma unroll
                for (int c = 0; c < 4; c++) sacc[nt][c] = 0.0f;
            #pragma unroll
            for (int ks = 0; ks < 4; ks++) {
                const int koff = ks * 16 + ((l15 >> 3) << 3);
                #pragma unroll
                for (int nt = 0; nt < 8; nt++) {
                    uint32_t b0, b1;
                    ldsm_x2(b0, b1, smaddr(&Ksc[(nt * 8 + (l15 & 7)) * KST + koff]));
                    MMA16(sacc[nt], qf[ks][0], qf[ks][1], qf[ks][2], qf[ks][3], b0, b1);
                }
            }

            if (ktile0 + 63 > roww) {
                #pragma unroll
                for (int nt = 0; nt < 8; nt++) {
                    const int c0 = ktile0 + nt * 8 + 2 * tg;
                    if (c0 > row0)     sacc[nt][0] = -1e30f;
                    if (c0 + 1 > row0) sacc[nt][1] = -1e30f;
                    if (c0 > row1)     sacc[nt][2] = -1e30f;
                    if (c0 + 1 > row1) sacc[nt][3] = -1e30f;
                }
            }

            float tm0 = -1e30f, tm1 = -1e30f;
            #pragma unroll
            for (int nt = 0; nt < 8; nt++) {
                tm0 = fmaxf(tm0, fmaxf(sacc[nt][0], sacc[nt][1]));
                tm1 = fmaxf(tm1, fmaxf(sacc[nt][2], sacc[nt][3]));
            }
            #pragma unroll
            for (int off = 1; off <= 2; off <<= 1) {
                tm0 = fmaxf(tm0, __shfl_xor_sync(0xffffffffu, tm0, off));
                tm1 = fmaxf(tm1, __shfl_xor_sync(0xffffffffu, tm1, off));
            }
            const float nm0 = fmaxf(m0, tm0), nm1 = fmaxf(m1, tm1);
            const float al0 = __expf(m0 - nm0), al1 = __expf(m1 - nm1);
            m0 = nm0; m1 = nm1;
            float ts0 = 0.0f, ts1 = 0.0f;
            #pragma unroll
            for (int nt = 0; nt < 8; nt++) {
                sacc[nt][0] = __expf(sacc[nt][0] - nm0);
                sacc[nt][1] = __expf(sacc[nt][1] - nm0);
                sacc[nt][2] = __expf(sacc[nt][2] - nm1);
                sacc[nt][3] = __expf(sacc[nt][3] - nm1);
                ts0 += sacc[nt][0] + sacc[nt][1];
                ts1 += sacc[nt][2] + sacc[nt][3];
            }
            #pragma unroll
            for (int off = 1; off <= 2; off <<= 1) {
                ts0 += __shfl_xor_sync(0xffffffffu, ts0, off);
                ts1 += __shfl_xor_sync(0xffffffffu, ts1, off);
            }
            l0 = l0 * al0 + ts0;
            l1 = l1 * al1 + ts1;
            #pragma unroll
            for (int nt = 0; nt < 8; nt++) {
                oacc[nt][0] *= al0; oacc[nt][1] *= al0;
                oacc[nt][2] *= al1; oacc[nt][3] *= al1;
            }

            // ---- O += P @ V (register repack) ----
            #pragma unroll
            for (int ks = 0; ks < 4; ks++) {
                const uint32_t a0 = h2pack(sacc[2*ks][0],   sacc[2*ks][1]);
                const uint32_t a1 = h2pack(sacc[2*ks][2],   sacc[2*ks][3]);
                const uint32_t a2 = h2pack(sacc[2*ks+1][0], sacc[2*ks+1][1]);
                const uint32_t a3 = h2pack(sacc[2*ks+1][2], sacc[2*ks+1][3]);
                #pragma unroll
                for (int nt = 0; nt < 8; nt++) {
                    uint32_t b0, b1;
                    ldsm_x2t(b0, b1, smaddr(&Vsc[(ks * 16 + l15) * VST + nt * 8]));
                    MMA16(oacc[nt], a0, a1, a2, a3, b0, b1);
                }
            }
        }
        if (jt + 1 <= jmax) CP_WAIT0();
        __syncthreads();
    }

    // ---- write O (fp16) ----
    const float inv0 = 1.0f / l0, inv1 = 1.0f / l1;
    const size_t ob0 = (size_t)(b * TT + row0) * DD + h * 64;
    const size_t ob1 = (size_t)(b * TT + row1) * DD + h * 64;
    #pragma unroll
    for (int nt = 0; nt < 8; nt++) {
        const int col = nt * 8 + 2 * tg;
        *reinterpret_cast<uint32_t*>(O + ob0 + col) = h2pack(oacc[nt][0] * inv0, oacc[nt][1] * inv0);
        *reinterpret_cast<uint32_t*>(O + ob1 + col) = h2pack(oacc[nt][2] * inv1, oacc[nt][3] * inv1);
    }
}

// ===================== launch =====================
extern "C" void kernel_launch(void* const* d_in, const int* in_sizes, int n_in,
                              void* d_out, int out_size) {
    (void)in_sizes; (void)n_in; (void)out_size;
    const float* x   = (const float*)d_in[0];
    const float* g1  = (const float*)d_in[1];
    const float* bt1 = (const float*)d_in[2];
    const float* wq  = (const float*)d_in[3];
    const float* bq  = (const float*)d_in[4];
    const float* wk  = (const float*)d_in[5];
    const float* bk  = (const float*)d_in[6];
    const float* wv  = (const float*)d_in[7];
    const float* bv  = (const float*)d_in[8];
    const float* wo  = (const float*)d_in[9];
    const float* bo  = (const float*)d_in[10];
    const float* g2  = (const float*)d_in[11];
    const float* bt2 = (const float*)d_in[12];
    const float* w1  = (const float*)d_in[13];
    const float* b1  = (const float*)d_in[14];
    const float* w2  = (const float*)d_in[15];
    const float* b2  = (const float*)d_in[16];
    float* out = (float*)d_out;

    __half *h1, *q, *k, *v, *ao, *h2, *f1;
    float* x1;
    __half *hwq, *hwk, *hwv, *hwo, *hw1, *hw2;
    cudaGetSymbolAddress((void**)&h1, g_h1);
    cudaGetSymbolAddress((void**)&q,  g_q);
    cudaGetSymbolAddress((void**)&k,  g_k);
    cudaGetSymbolAddress((void**)&v,  g_v);
    cudaGetSymbolAddress((void**)&ao, g_ao);
    cudaGetSymbolAddress((void**)&x1, g_x1);
    cudaGetSymbolAddress((void**)&h2, g_h2);
    cudaGetSymbolAddress((void**)&f1, g_f1);
    cudaGetSymbolAddress((void**)&hwq, g_wq);
    cudaGetSymbolAddress((void**)&hwk, g_wk);
    cudaGetSymbolAddress((void**)&hwv, g_wv);
    cudaGetSymbolAddress((void**)&hwo, g_wo);
    cudaGetSymbolAddress((void**)&hw1, g_w1);
    cudaGetSymbolAddress((void**)&hw2, g_w2);

    const int ATTN_SMEM = ATTN_HALVES * (int)sizeof(__half);
    cudaFuncSetAttribute(attn_h, cudaFuncAttributeMaxDynamicSharedMemorySize, ATTN_SMEM);

    // 0. weights fp32 -> fp16
    cvt_w<<<(C5 + 255) / 256, 256>>>(wq, wk, wv, wo, w1, w2, hwq, hwk, hwv, hwo, hw1, hw2);
    // 1. h1 = LN(x)
    ln_kernel<<<RR, 256>>>(x, g1, bt1, h1);
    // 2. fused q/k/v (q pre-scaled by 0.125)
    gemm_qkv<<<dim3(12, RR / 128), 256>>>(h1, hwq, bq, hwk, bk, hwv, bv, q, k, v);
    // 3. attention
    attn_h<<<dim3(TT / 128, 16, BB), 256, ATTN_SMEM>>>(q, k, v, ao);
    // 4. x1 = x + ao @ wo + bo   (fp32 out)
    gemm_h<2, false><<<dim3(DD / 128, RR / 128), 256>>>(ao, hwo, bo, x, x1, DD, DD);
    // 5. h2 = LN(x1)
    ln_kernel<<<RR, 256>>>(x1, g2, bt2, h2);
    // 6. f1 = gelu(h2 @ w1 + b1)  (fp16 out)
    gemm_h<1, true><<<dim3(4 * DD / 128, RR / 128), 256>>>(h2, hw1, b1, nullptr, f1, 4 * DD, DD);
    // 7. out = x1 + f1 @ w2 + b2  (fp32 out)
    gemm_h<2, false><<<dim3(DD / 128, RR / 128), 256>>>(f1, hw2, b2, x1, out, DD, 4 * DD);
}

// round 6
// speedup vs baseline: 7.6613x; 1.0767x over previous
#include <cuda_runtime.h>
#include <cuda_fp16.h>
#include <math.h>
#include <stdint.h>

#define BB 2
#define TT 2048
#define DD 1024
#define RR (BB*TT)   // 4096 rows

// -------- scratch (device globals; no runtime allocation) --------
__device__ __half g_h1[RR*DD];
__device__ __half g_q [RR*DD];
__device__ __half g_k [RR*256];
__device__ __half g_v [RR*256];
__device__ __half g_ao[RR*DD];
__device__ float  g_x1[RR*DD];
__device__ __half g_h2[RR*DD];
__device__ __half g_f1[RR*4*DD];
// fp16 weights
__device__ __half g_wq[DD*DD];
__device__ __half g_wk[DD*256];
__device__ __half g_wv[DD*256];
__device__ __half g_wo[DD*DD];
__device__ __half g_w1[DD*4*DD];
__device__ __half g_w2[4*DD*DD];

__device__ __forceinline__ uint32_t smaddr(const void* p) {
    return (uint32_t)__cvta_generic_to_shared(p);
}
__device__ __forceinline__ void cp16(uint32_t dst, const void* src) {
    asm volatile("cp.async.cg.shared.global [%0], [%1], 16;" :: "r"(dst), "l"(src));
}
#define CP_COMMIT() asm volatile("cp.async.commit_group;" ::: "memory")
#define CP_WAIT0()  asm volatile("cp.async.wait_group 0;" ::: "memory")

__device__ __forceinline__ void ldsm_x4(uint32_t& r0, uint32_t& r1, uint32_t& r2, uint32_t& r3, uint32_t a) {
    asm volatile("ldmatrix.sync.aligned.m8n8.x4.shared.b16 {%0,%1,%2,%3}, [%4];"
                 : "=r"(r0), "=r"(r1), "=r"(r2), "=r"(r3) : "r"(a));
}
__device__ __forceinline__ void ldsm_x2(uint32_t& r0, uint32_t& r1, uint32_t a) {
    asm volatile("ldmatrix.sync.aligned.m8n8.x2.shared.b16 {%0,%1}, [%2];"
                 : "=r"(r0), "=r"(r1) : "r"(a));
}
__device__ __forceinline__ void ldsm_x2t(uint32_t& r0, uint32_t& r1, uint32_t a) {
    asm volatile("ldmatrix.sync.aligned.m8n8.x2.trans.shared.b16 {%0,%1}, [%2];"
                 : "=r"(r0), "=r"(r1) : "r"(a));
}
#define MMA16(c, a0,a1,a2,a3, b0,b1) \
    asm volatile("mma.sync.aligned.m16n8k16.row.col.f32.f16.f16.f32 " \
                 "{%0,%1,%2,%3}, {%4,%5,%6,%7}, {%8,%9}, {%0,%1,%2,%3};" \
                 : "+f"((c)[0]), "+f"((c)[1]), "+f"((c)[2]), "+f"((c)[3]) \
                 : "r"(a0), "r"(a1), "r"(a2), "r"(a3), "r"(b0), "r"(b1))

__device__ __forceinline__ uint32_t h2pack(float x, float y) {
    __half2 h = __floats2half2_rn(x, y);
    return *reinterpret_cast<uint32_t*>(&h);
}
__device__ __forceinline__ float ex2f(float x) {
    float y;
    asm("ex2.approx.ftz.f32 %0, %1;" : "=f"(y) : "f"(x));
    return y;
}

// ===================== weight conversion (fp32 -> fp16) =====================
#define C0 262144
#define C1 327680
#define C2 393216
#define C3 655360
#define C4 1703936
#define C5 2752512
__global__ void cvt_w(const float* __restrict__ s0, const float* __restrict__ s1,
                      const float* __restrict__ s2, const float* __restrict__ s3,
                      const float* __restrict__ s4, const float* __restrict__ s5,
                      __half* d0, __half* d1, __half* d2,
                      __half* d3, __half* d4, __half* d5) {
    const int i = blockIdx.x * blockDim.x + threadIdx.x;
    if (i >= C5) return;
    const float* s; __half* d; int base;
    if      (i < C0) { s = s0; d = d0; base = 0;  }
    else if (i < C1) { s = s1; d = d1; base = C0; }
    else if (i < C2) { s = s2; d = d2; base = C1; }
    else if (i < C3) { s = s3; d = d3; base = C2; }
    else if (i < C4) { s = s4; d = d4; base = C3; }
    else             { s = s5; d = d5; base = C4; }
    const int j = i - base;
    float4 v = reinterpret_cast<const float4*>(s)[j];
    uint2 u = { h2pack(v.x, v.y), h2pack(v.z, v.w) };
    reinterpret_cast<uint2*>(d)[j] = u;
}

// ===================== LayerNorm (fp32 in, fp16 out) =====================
__device__ __forceinline__ float block_sum256(float v, float* sh) {
    #pragma unroll
    for (int o = 16; o; o >>= 1) v += __shfl_xor_sync(0xffffffffu, v, o);
    if ((threadIdx.x & 31) == 0) sh[threadIdx.x >> 5] = v;
    __syncthreads();
    float t = sh[threadIdx.x & 7];
    #pragma unroll
    for (int o = 4; o; o >>= 1) t += __shfl_xor_sync(0xffffffffu, t, o);
    __syncthreads();
    return t;
}

__global__ void ln_kernel(const float* __restrict__ x, const float* __restrict__ gw,
                          const float* __restrict__ bw, __half* __restrict__ out) {
    __shared__ float sh[8];
    const int row = blockIdx.x;
    const float4* xr = reinterpret_cast<const float4*>(x + (size_t)row * DD);
    float4 v = xr[threadIdx.x];
    float s = v.x + v.y + v.z + v.w;
    float tot = block_sum256(s, sh);
    float mean = tot * (1.0f / DD);
    float dx = v.x - mean, dy = v.y - mean, dz = v.z - mean, dw = v.w - mean;
    float s2 = dx*dx + dy*dy + dz*dz + dw*dw;
    float tot2 = block_sum256(s2, sh);
    float rstd = rsqrtf(tot2 * (1.0f / DD) + 1e-5f);
    float4 g4 = reinterpret_cast<const float4*>(gw)[threadIdx.x];
    float4 b4 = reinterpret_cast<const float4*>(bw)[threadIdx.x];
    uint2 o = { h2pack(g4.x * dx * rstd + b4.x, g4.y * dy * rstd + b4.y),
                h2pack(g4.z * dz * rstd + b4.z, g4.w * dw * rstd + b4.w) };
    reinterpret_cast<uint2*>(out + (size_t)row * DD)[threadIdx.x] = o;
}

// ===================== FP16 tensor-core GEMM (cp.async, k-step 64) =====================
// 128x128 CTA tile, k-step 64, 8 warps (2x4), warp 64x32, mma.m16n8k16.
#define AST 72    // halves per A smem row (64 + 8 pad)
#define BST 136   // halves per B smem row (128 + 8 pad)
#define A_BUF (128 * AST)
#define B_BUF (64 * BST)
#define GEMM_SMEM ((2 * A_BUF + 2 * B_BUF) * (int)sizeof(__half))

// EPI: 0 none, 1 GELU, 2 +=res ; OUTH: output half (else float)
template<int EPI, bool OUTH>
__device__ __forceinline__ void gemm_body_h(
    const __half* __restrict__ A, const __half* __restrict__ Bm,
    const float* __restrict__ bias, const float* __restrict__ res,
    void* __restrict__ C, int N, int K, int brow, int bcol,
    __half* As, __half* Bs, float oscale) {

    const int tid  = threadIdx.x;
    const int lane = tid & 31, wid = tid >> 5;
    const int wm = wid & 1, wn = wid >> 1;
    const int g  = lane >> 2, tg = lane & 3;
    const int l15 = lane & 15;

    float acc[4][4][4];
    #pragma unroll
    for (int mt = 0; mt < 4; mt++)
        #pragma unroll
        for (int nt = 0; nt < 4; nt++)
            #pragma unroll
            for (int c = 0; c < 4; c++) acc[mt][nt][c] = 0.0f;

    // prologue: tile 0 (A 128x64h: 1024 chunks; B 64x128h: 1024 chunks)
    #pragma unroll
    for (int r = 0; r < 4; r++) {
        const int f = tid + (r << 8);
        cp16(smaddr(&As[(f >> 3) * AST + ((f & 7) << 3)]),
             A + (size_t)(brow + (f >> 3)) * K + ((f & 7) << 3));
        cp16(smaddr(&Bs[(f >> 4) * BST + ((f & 15) << 3)]),
             Bm + (size_t)(f >> 4) * N + bcol + ((f & 15) << 3));
    }
    CP_COMMIT();
    CP_WAIT0();
    __syncthreads();

    const int nk = K >> 6;
    for (int kt = 0; kt < nk; kt++) {
        const int cur = kt & 1;
        __half* Asc = As + cur * A_BUF;
        __half* Bsc = Bs + cur * B_BUF;
        if (kt + 1 < nk) {
            const int k0 = (kt + 1) << 6;
            __half* Asn = As + (cur ^ 1) * A_BUF;
            __half* Bsn = Bs + (cur ^ 1) * B_BUF;
            #pragma unroll
            for (int r = 0; r < 4; r++) {
                const int f = tid + (r << 8);
                cp16(smaddr(&Asn[(f >> 3) * AST + ((f & 7) << 3)]),
                     A + (size_t)(brow + (f >> 3)) * K + k0 + ((f & 7) << 3));
                cp16(smaddr(&Bsn[(f >> 4) * BST + ((f & 15) << 3)]),
                     Bm + (size_t)(k0 + (f >> 4)) * N + bcol + ((f & 15) << 3));
            }
            CP_COMMIT();
        }
        #pragma unroll
        for (int ks = 0; ks < 4; ks++) {
            uint32_t af[4][4], bf[4][2];
            const int koff = ks * 16 + ((lane >> 4) << 3);
            #pragma unroll
            for (int mt = 0; mt < 4; mt++)
                ldsm_x4(af[mt][0], af[mt][1], af[mt][2], af[mt][3],
                        smaddr(&Asc[(wm * 64 + mt * 16 + l15) * AST + koff]));
            #pragma unroll
            for (int nt = 0; nt < 4; nt++)
                ldsm_x2t(bf[nt][0], bf[nt][1],
                         smaddr(&Bsc[(ks * 16 + l15) * BST + wn * 32 + nt * 8]));
            #pragma unroll
            for (int mt = 0; mt < 4; mt++)
                #pragma unroll
                for (int nt = 0; nt < 4; nt++)
                    MMA16(acc[mt][nt], af[mt][0], af[mt][1], af[mt][2], af[mt][3],
                          bf[nt][0], bf[nt][1]);
        }
        if (kt + 1 < nk) CP_WAIT0();
        __syncthreads();
    }

    #pragma unroll
    for (int mt = 0; mt < 4; mt++) {
        #pragma unroll
        for (int half = 0; half < 2; half++) {
            const int row = brow + wm * 64 + mt * 16 + g + half * 8;
            #pragma unroll
            for (int nt = 0; nt < 4; nt++) {
                const int col = bcol + wn * 32 + nt * 8 + tg * 2;
                float v0 = acc[mt][nt][half * 2 + 0] + bias[col];
                float v1 = acc[mt][nt][half * 2 + 1] + bias[col + 1];
                if (EPI == 1) {
                    v0 = 0.5f * v0 * (1.0f + erff(v0 * 0.70710678118654752f));
                    v1 = 0.5f * v1 * (1.0f + erff(v1 * 0.70710678118654752f));
                }
                if (EPI == 2) {
                    float2 rr = *reinterpret_cast<const float2*>(res + (size_t)row * N + col);
                    v0 += rr.x; v1 += rr.y;
                }
                v0 *= oscale; v1 *= oscale;
                if (OUTH) {
                    *reinterpret_cast<uint32_t*>((__half*)C + (size_t)row * N + col) = h2pack(v0, v1);
                } else {
                    float2 o2; o2.x = v0; o2.y = v1;
                    *reinterpret_cast<float2*>((float*)C + (size_t)row * N + col) = o2;
                }
            }
        }
    }
}

template<int EPI, bool OUTH>
__global__ void __launch_bounds__(256, 2)
gemm_h(const __half* __restrict__ A, const __half* __restrict__ Bm,
       const float* __restrict__ bias, const float* __restrict__ res,
       void* __restrict__ C, int N, int K) {
    extern __shared__ __half smg[];
    __half* As = smg;
    __half* Bs = smg + 2 * A_BUF;
    gemm_body_h<EPI, OUTH>(A, Bm, bias, res, C, N, K, blockIdx.y * 128, blockIdx.x * 128, As, Bs, 1.0f);
}

// fused QKV: grid.x = 12 (8 q tiles, 2 k tiles, 2 v tiles)
// Q pre-scaled by 0.125 * log2(e) so attention can use ex2 directly.
#define QSCALE (0.125f * 1.4426950408889634f)
__global__ void __launch_bounds__(256, 2)
gemm_qkv(const __half* __restrict__ A,
         const __half* __restrict__ wq, const float* __restrict__ bq,
         const __half* __restrict__ wk, const float* __restrict__ bk,
         const __half* __restrict__ wv, const float* __restrict__ bv,
         __half* __restrict__ q, __half* __restrict__ k, __half* __restrict__ v) {
    extern __shared__ __half smg[];
    __half* As = smg;
    __half* Bs = smg + 2 * A_BUF;
    const int bx = blockIdx.x;
    const __half* Bm; const float* bias; __half* C; int N, bcol; float sc;
    if (bx < 8)       { Bm = wq; bias = bq; C = q; N = 1024; bcol = bx * 128;        sc = QSCALE; }
    else if (bx < 10) { Bm = wk; bias = bk; C = k; N = 256;  bcol = (bx - 8) * 128;  sc = 1.0f; }
    else              { Bm = wv; bias = bv; C = v; N = 256;  bcol = (bx - 10) * 128; sc = 1.0f; }
    gemm_body_h<0, true>(A, Bm, bias, nullptr, C, N, DD, blockIdx.y * 128, bcol, As, Bs, sc);
}

// ===================== Flash attention (fp16 mma, causal, GQA) =====================
// grid (T/128, 16, B), 256 threads (8 warps, each owns 16 q rows)
// K/V double-buffered cp.async; scores in log2e domain (Q pre-scaled).
#define QST 72
#define KST 72
#define VST 72
#define ATTN_HALVES (128*QST + 2*64*KST + 2*64*VST)

__global__ void __launch_bounds__(256, 2)
attn_h(const __half* __restrict__ Q, const __half* __restrict__ K,
       const __half* __restrict__ V, __half* __restrict__ O) {
    extern __shared__ __half smh[];
    __half* Qs = smh;
    __half* Ks = smh + 128 * QST;
    __half* Vs = Ks + 2 * 64 * KST;

    const int tid = threadIdx.x;
    const int lane = tid & 31, w = tid >> 5;
    const int g = lane >> 2, tg = lane & 3;
    const int l15 = lane & 15;
    const int h = blockIdx.y, b = blockIdx.z, grp = h >> 2;
    const int bx = (int)gridDim.x - 1 - (int)blockIdx.x;   // longest-work CTAs first
    const int q0 = bx << 7;

    {
        const size_t qbase = (size_t)(b * TT + q0) * DD + h * 64;
        #pragma unroll
        for (int i = 0; i < 4; i++) {
            const int f = tid + (i << 8);
            const int r = f >> 3, c = (f & 7) << 3;
            cp16(smaddr(&Qs[r * QST + c]), Q + qbase + (size_t)r * DD + c);
        }
    }
    {
        const size_t kvbase = (size_t)(b * TT) * 256 + grp * 64;
        #pragma unroll
        for (int i = 0; i < 2; i++) {
            const int f = tid + (i << 8);
            const int r = f >> 3, c = (f & 7) << 3;
            cp16(smaddr(&Ks[r * KST + c]), K + kvbase + (size_t)r * 256 + c);
            cp16(smaddr(&Vs[r * VST + c]), V + kvbase + (size_t)r * 256 + c);
        }
    }
    CP_COMMIT();
    CP_WAIT0();
    __syncthreads();

    uint32_t qf[4][4];
    {
        const int koff = (lane >> 4) << 3;
        #pragma unroll
        for (int ks = 0; ks < 4; ks++)
            ldsm_x4(qf[ks][0], qf[ks][1], qf[ks][2], qf[ks][3],
                    smaddr(&Qs[(w * 16 + l15) * QST + ks * 16 + koff]));
    }

    float oacc[8][4];
    #pragma unroll
    for (int nt = 0; nt < 8; nt++)
        #pragma unroll
        for (int c = 0; c < 4; c++) oacc[nt][c] = 0.0f;
    float m0 = -1e30f, m1 = -1e30f, l0 = 0.0f, l1 = 0.0f;

    const int roww = q0 + w * 16;
    const int row0 = roww + g, row1 = roww + g + 8;

    const int jmax = 2 * bx + 1;
    for (int jt = 0; jt <= jmax; jt++) {
        const int cur = jt & 1;
        __half* Ksc = Ks + cur * (64 * KST);
        __half* Vsc = Vs + cur * (64 * VST);
        if (jt + 1 <= jmax) {
            __half* Ksn = Ks + (cur ^ 1) * (64 * KST);
            __half* Vsn = Vs + (cur ^ 1) * (64 * VST);
            const size_t kvbase = (size_t)(b * TT + ((jt + 1) << 6)) * 256 + grp * 64;
            #pragma unroll
            for (int i = 0; i < 2; i++) {
                const int f = tid + (i << 8);
                const int r = f >> 3, c = (f & 7) << 3;
                cp16(smaddr(&Ksn[r * KST + c]), K + kvbase + (size_t)r * 256 + c);
                cp16(smaddr(&Vsn[r * VST + c]), V + kvbase + (size_t)r * 256 + c);
            }
            CP_COMMIT();
        }

        const int ktile0 = jt << 6;
        if (ktile0 <= roww + 15) {
            // ---- S = Q K^T (log2e domain) ----
            float sacc[8][4];
            #pragma unroll
            for (int nt = 0; nt < 8; nt++)
                #pragma unroll
                for (int c = 0; c < 4; c++) sacc[nt][c] = 0.0f;
            #pragma unroll
            for (int ks = 0; ks < 4; ks++) {
                const int koff = ks * 16 + ((l15 >> 3) << 3);
                #pragma unroll
                for (int nt = 0; nt < 8; nt++) {
                    uint32_t b0, b1;
                    ldsm_x2(b0, b1, smaddr(&Ksc[(nt * 8 + (l15 & 7)) * KST + koff]));
                    MMA16(sacc[nt], qf[ks][0], qf[ks][1], qf[ks][2], qf[ks][3], b0, b1);
                }
            }

            if (ktile0 + 63 > roww) {
                #pragma unroll
                for (int nt = 0; nt < 8; nt++) {
                    const int c0 = ktile0 + nt * 8 + 2 * tg;
                    if (c0 > row0)     sacc[nt][0] = -1e30f;
                    if (c0 + 1 > row0) sacc[nt][1] = -1e30f;
                    if (c0 > row1)     sacc[nt][2] = -1e30f;
                    if (c0 + 1 > row1) sacc[nt][3] = -1e30f;
                }
            }

            float tm0 = -1e30f, tm1 = -1e30f;
            #pragma unroll
            for (int nt = 0; nt < 8; nt++) {
                tm0 = fmaxf(tm0, fmaxf(sacc[nt][0], sacc[nt][1]));
                tm1 = fmaxf(tm1, fmaxf(sacc[nt][2], sacc[nt][3]));
            }
            #pragma unroll
            for (int off = 1; off <= 2; off <<= 1) {
                tm0 = fmaxf(tm0, __shfl_xor_sync(0xffffffffu, tm0, off));
                tm1 = fmaxf(tm1, __shfl_xor_sync(0xffffffffu, tm1, off));
            }
            const float nm0 = fmaxf(m0, tm0), nm1 = fmaxf(m1, tm1);
            const float al0 = ex2f(m0 - nm0), al1 = ex2f(m1 - nm1);
            m0 = nm0; m1 = nm1;
            float ts0 = 0.0f, ts1 = 0.0f;
            #pragma unroll
            for (int nt = 0; nt < 8; nt++) {
                sacc[nt][0] = ex2f(sacc[nt][0] - nm0);
                sacc[nt][1] = ex2f(sacc[nt][1] - nm0);
                sacc[nt][2] = ex2f(sacc[nt][2] - nm1);
                sacc[nt][3] = ex2f(sacc[nt][3] - nm1);
                ts0 += sacc[nt][0] + sacc[nt][1];
                ts1 += sacc[nt][2] + sacc[nt][3];
            }
            #pragma unroll
            for (int off = 1; off <= 2; off <<= 1) {
                ts0 += __shfl_xor_sync(0xffffffffu, ts0, off);
                ts1 += __shfl_xor_sync(0xffffffffu, ts1, off);
            }
            l0 = l0 * al0 + ts0;
            l1 = l1 * al1 + ts1;
            #pragma unroll
            for (int nt = 0; nt < 8; nt++) {
                oacc[nt][0] *= al0; oacc[nt][1] *= al0;
                oacc[nt][2] *= al1; oacc[nt][3] *= al1;
            }

            // ---- O += P @ V (register repack) ----
            #pragma unroll
            for (int ks = 0; ks < 4; ks++) {
                const uint32_t a0 = h2pack(sacc[2*ks][0],   sacc[2*ks][1]);
                const uint32_t a1 = h2pack(sacc[2*ks][2],   sacc[2*ks][3]);
                const uint32_t a2 = h2pack(sacc[2*ks+1][0], sacc[2*ks+1][1]);
                const uint32_t a3 = h2pack(sacc[2*ks+1][2], sacc[2*ks+1][3]);
                #pragma unroll
                for (int nt = 0; nt < 8; nt++) {
                    uint32_t b0, b1;
                    ldsm_x2t(b0, b1, smaddr(&Vsc[(ks * 16 + l15) * VST + nt * 8]));
                    MMA16(oacc[nt], a0, a1, a2, a3, b0, b1);
                }
            }
        }
        if (jt + 1 <= jmax) CP_WAIT0();
        __syncthreads();
    }

    const float inv0 = 1.0f / l0, inv1 = 1.0f / l1;
    const size_t ob0 = (size_t)(b * TT + row0) * DD + h * 64;
    const size_t ob1 = (size_t)(b * TT + row1) * DD + h * 64;
    #pragma unroll
    for (int nt = 0; nt < 8; nt++) {
        const int col = nt * 8 + 2 * tg;
        *reinterpret_cast<uint32_t*>(O + ob0 + col) = h2pack(oacc[nt][0] * inv0, oacc[nt][1] * inv0);
        *reinterpret_cast<uint32_t*>(O + ob1 + col) = h2pack(oacc[nt][2] * inv1, oacc[nt][3] * inv1);
    }
}

// ===================== launch =====================
extern "C" void kernel_launch(void* const* d_in, const int* in_sizes, int n_in,
                              void* d_out, int out_size) {
    (void)in_sizes; (void)n_in; (void)out_size;
    const float* x   = (const float*)d_in[0];
    const float* g1  = (const float*)d_in[1];
    const float* bt1 = (const float*)d_in[2];
    const float* wq  = (const float*)d_in[3];
    const float* bq  = (const float*)d_in[4];
    const float* wk  = (const float*)d_in[5];
    const float* bk  = (const float*)d_in[6];
    const float* wv  = (const float*)d_in[7];
    const float* bv  = (const float*)d_in[8];
    const float* wo  = (const float*)d_in[9];
    const float* bo  = (const float*)d_in[10];
    const float* g2  = (const float*)d_in[11];
    const float* bt2 = (const float*)d_in[12];
    const float* w1  = (const float*)d_in[13];
    const float* b1  = (const float*)d_in[14];
    const float* w2  = (const float*)d_in[15];
    const float* b2  = (const float*)d_in[16];
    float* out = (float*)d_out;

    __half *h1, *q, *k, *v, *ao, *h2, *f1;
    float* x1;
    __half *hwq, *hwk, *hwv, *hwo, *hw1, *hw2;
    cudaGetSymbolAddress((void**)&h1, g_h1);
    cudaGetSymbolAddress((void**)&q,  g_q);
    cudaGetSymbolAddress((void**)&k,  g_k);
    cudaGetSymbolAddress((void**)&v,  g_v);
    cudaGetSymbolAddress((void**)&ao, g_ao);
    cudaGetSymbolAddress((void**)&x1, g_x1);
    cudaGetSymbolAddress((void**)&h2, g_h2);
    cudaGetSymbolAddress((void**)&f1, g_f1);
    cudaGetSymbolAddress((void**)&hwq, g_wq);
    cudaGetSymbolAddress((void**)&hwk, g_wk);
    cudaGetSymbolAddress((void**)&hwv, g_wv);
    cudaGetSymbolAddress((void**)&hwo, g_wo);
    cudaGetSymbolAddress((void**)&hw1, g_w1);
    cudaGetSymbolAddress((void**)&hw2, g_w2);

    const int ATTN_SMEM = ATTN_HALVES * (int)sizeof(__half);
    cudaFuncSetAttribute(attn_h, cudaFuncAttributeMaxDynamicSharedMemorySize, ATTN_SMEM);
    cudaFuncSetAttribute(gemm_h<0, true>,  cudaFuncAttributeMaxDynamicSharedMemorySize, GEMM_SMEM);
    cudaFuncSetAttribute(gemm_h<1, true>,  cudaFuncAttributeMaxDynamicSharedMemorySize, GEMM_SMEM);
    cudaFuncSetAttribute(gemm_h<2, false>, cudaFuncAttributeMaxDynamicSharedMemorySize, GEMM_SMEM);
    cudaFuncSetAttribute(gemm_qkv,         cudaFuncAttributeMaxDynamicSharedMemorySize, GEMM_SMEM);

    // 0. weights fp32 -> fp16
    cvt_w<<<(C5 + 255) / 256, 256>>>(wq, wk, wv, wo, w1, w2, hwq, hwk, hwv, hwo, hw1, hw2);
    // 1. h1 = LN(x)
    ln_kernel<<<RR, 256>>>(x, g1, bt1, h1);
    // 2. fused q/k/v (q pre-scaled by 0.125*log2e)
    gemm_qkv<<<dim3(12, RR / 128), 256, GEMM_SMEM>>>(h1, hwq, bq, hwk, bk, hwv, bv, q, k, v);
    // 3. attention
    attn_h<<<dim3(TT / 128, 16, BB), 256, ATTN_SMEM>>>(q, k, v, ao);
    // 4. x1 = x + ao @ wo + bo   (fp32 out)
    gemm_h<2, false><<<dim3(DD / 128, RR / 128), 256, GEMM_SMEM>>>(ao, hwo, bo, x, x1, DD, DD);
    // 5. h2 = LN(x1)
    ln_kernel<<<RR, 256>>>(x1, g2, bt2, h2);
    // 6. f1 = gelu(h2 @ w1 + b1)  (fp16 out)
    gemm_h<1, true><<<dim3(4 * DD / 128, RR / 128), 256, GEMM_SMEM>>>(h2, hw1, b1, nullptr, f1, 4 * DD, DD);
    // 7. out = x1 + f1 @ w2 + b2  (fp32 out)
    gemm_h<2, false><<<dim3(DD / 128, RR / 128), 256, GEMM_SMEM>>>(f1, hw2, b2, x1, out, DD, 4 * DD);
}

// round 7
// speedup vs baseline: 7.7555x; 1.0123x over previous
#include <cuda_runtime.h>
#include <cuda_fp16.h>
#include <math.h>
#include <stdint.h>

#define BB 2
#define TT 2048
#define DD 1024
#define RR (BB*TT)   // 4096 rows

// -------- scratch (device globals; no runtime allocation) --------
__device__ __half g_h1[RR*DD];
__device__ __half g_q [RR*DD];
__device__ __half g_k [RR*256];
__device__ __half g_v [RR*256];
__device__ __half g_ao[RR*DD];
__device__ float  g_x1[RR*DD];
__device__ __half g_h2[RR*DD];
__device__ __half g_f1[RR*4*DD];
// fp16 weights
__device__ __half g_wq[DD*DD];
__device__ __half g_wk[DD*256];
__device__ __half g_wv[DD*256];
__device__ __half g_wo[DD*DD];
__device__ __half g_w1[DD*4*DD];
__device__ __half g_w2[4*DD*DD];

__device__ __forceinline__ uint32_t smaddr(const void* p) {
    return (uint32_t)__cvta_generic_to_shared(p);
}
__device__ __forceinline__ void cp16(uint32_t dst, const void* src) {
    asm volatile("cp.async.cg.shared.global [%0], [%1], 16;" :: "r"(dst), "l"(src));
}
#define CP_COMMIT() asm volatile("cp.async.commit_group;" ::: "memory")
#define CP_WAIT(n)  asm volatile("cp.async.wait_group %0;" :: "n"(n) : "memory")

__device__ __forceinline__ void ldsm_x4(uint32_t& r0, uint32_t& r1, uint32_t& r2, uint32_t& r3, uint32_t a) {
    asm volatile("ldmatrix.sync.aligned.m8n8.x4.shared.b16 {%0,%1,%2,%3}, [%4];"
                 : "=r"(r0), "=r"(r1), "=r"(r2), "=r"(r3) : "r"(a));
}
__device__ __forceinline__ void ldsm_x4t(uint32_t& r0, uint32_t& r1, uint32_t& r2, uint32_t& r3, uint32_t a) {
    asm volatile("ldmatrix.sync.aligned.m8n8.x4.trans.shared.b16 {%0,%1,%2,%3}, [%4];"
                 : "=r"(r0), "=r"(r1), "=r"(r2), "=r"(r3) : "r"(a));
}
#define MMA16(c, a0,a1,a2,a3, b0,b1) \
    asm volatile("mma.sync.aligned.m16n8k16.row.col.f32.f16.f16.f32 " \
                 "{%0,%1,%2,%3}, {%4,%5,%6,%7}, {%8,%9}, {%0,%1,%2,%3};" \
                 : "+f"((c)[0]), "+f"((c)[1]), "+f"((c)[2]), "+f"((c)[3]) \
                 : "r"(a0), "r"(a1), "r"(a2), "r"(a3), "r"(b0), "r"(b1))

__device__ __forceinline__ uint32_t h2pack(float x, float y) {
    __half2 h = __floats2half2_rn(x, y);
    return *reinterpret_cast<uint32_t*>(&h);
}
__device__ __forceinline__ float ex2f(float x) {
    float y;
    asm("ex2.approx.ftz.f32 %0, %1;" : "=f"(y) : "f"(x));
    return y;
}

// ===================== weight conversion (fp32 -> fp16) =====================
#define C0 262144
#define C1 327680
#define C2 393216
#define C3 655360
#define C4 1703936
#define C5 2752512
__global__ void cvt_w(const float* __restrict__ s0, const float* __restrict__ s1,
                      const float* __restrict__ s2, const float* __restrict__ s3,
                      const float* __restrict__ s4, const float* __restrict__ s5,
                      __half* d0, __half* d1, __half* d2,
                      __half* d3, __half* d4, __half* d5) {
    const int i = blockIdx.x * blockDim.x + threadIdx.x;
    if (i >= C5) return;
    const float* s; __half* d; int base;
    if      (i < C0) { s = s0; d = d0; base = 0;  }
    else if (i < C1) { s = s1; d = d1; base = C0; }
    else if (i < C2) { s = s2; d = d2; base = C1; }
    else if (i < C3) { s = s3; d = d3; base = C2; }
    else if (i < C4) { s = s4; d = d4; base = C3; }
    else             { s = s5; d = d5; base = C4; }
    const int j = i - base;
    float4 v = reinterpret_cast<const float4*>(s)[j];
    uint2 u = { h2pack(v.x, v.y), h2pack(v.z, v.w) };
    reinterpret_cast<uint2*>(d)[j] = u;
}

// ===================== LayerNorm (fp32 in, fp16 out) =====================
__device__ __forceinline__ float block_sum256(float v, float* sh) {
    #pragma unroll
    for (int o = 16; o; o >>= 1) v += __shfl_xor_sync(0xffffffffu, v, o);
    if ((threadIdx.x & 31) == 0) sh[threadIdx.x >> 5] = v;
    __syncthreads();
    float t = sh[threadIdx.x & 7];
    #pragma unroll
    for (int o = 4; o; o >>= 1) t += __shfl_xor_sync(0xffffffffu, t, o);
    __syncthreads();
    return t;
}

__global__ void ln_kernel(const float* __restrict__ x, const float* __restrict__ gw,
                          const float* __restrict__ bw, __half* __restrict__ out) {
    __shared__ float sh[8];
    const int row = blockIdx.x;
    const float4* xr = reinterpret_cast<const float4*>(x + (size_t)row * DD);
    float4 v = xr[threadIdx.x];
    float s = v.x + v.y + v.z + v.w;
    float tot = block_sum256(s, sh);
    float mean = tot * (1.0f / DD);
    float dx = v.x - mean, dy = v.y - mean, dz = v.z - mean, dw = v.w - mean;
    float s2 = dx*dx + dy*dy + dz*dz + dw*dw;
    float tot2 = block_sum256(s2, sh);
    float rstd = rsqrtf(tot2 * (1.0f / DD) + 1e-5f);
    float4 g4 = reinterpret_cast<const float4*>(gw)[threadIdx.x];
    float4 b4 = reinterpret_cast<const float4*>(bw)[threadIdx.x];
    uint2 o = { h2pack(g4.x * dx * rstd + b4.x, g4.y * dy * rstd + b4.y),
                h2pack(g4.z * dz * rstd + b4.z, g4.w * dw * rstd + b4.w) };
    reinterpret_cast<uint2*>(out + (size_t)row * DD)[threadIdx.x] = o;
}

// ===================== FP16 tensor-core GEMM (3-stage cp.async, k-step 64) =====================
#define AST 72    // halves per A smem row (64 + 8 pad)
#define BST 136   // halves per B smem row (128 + 8 pad)
#define A_BUF (128 * AST)
#define B_BUF (64 * BST)
#define GEMM_SMEM (3 * (A_BUF + B_BUF) * (int)sizeof(__half))

template<int EPI, bool OUTH>
__device__ __forceinline__ void gemm_body_h(
    const __half* __restrict__ A, const __half* __restrict__ Bm,
    const float* __restrict__ bias, const float* __restrict__ res,
    void* __restrict__ C, int N, int K, int brow, int bcol,
    __half* Ab, __half* Bb, float oscale) {

    const int tid  = threadIdx.x;
    const int lane = tid & 31, wid = tid >> 5;
    const int wm = wid & 1, wn = wid >> 1;
    const int g  = lane >> 2, tg = lane & 3;
    const int l15 = lane & 15;

    __half* Asv[3] = { Ab, Ab + A_BUF, Ab + 2 * A_BUF };
    __half* Bsv[3] = { Bb, Bb + B_BUF, Bb + 2 * B_BUF };

    float acc[4][4][4];
    #pragma unroll
    for (int mt = 0; mt < 4; mt++)
        #pragma unroll
        for (int nt = 0; nt < 4; nt++)
            #pragma unroll
            for (int c = 0; c < 4; c++) acc[mt][nt][c] = 0.0f;

    // per-thread copy coords (A: 1024 chunks of 8h; B: 1024 chunks)
    const int arow = tid >> 3, acol = (tid & 7) << 3;
    const int brw  = tid >> 4, bcl  = (tid & 15) << 3;

    const int nk = K >> 6;   // >= 16 always here
    // prologue: stages 0 and 1
    #pragma unroll
    for (int s = 0; s < 2; s++) {
        const int k0 = s << 6;
        #pragma unroll
        for (int r = 0; r < 4; r++) {
            cp16(smaddr(&Asv[s][(arow + r * 32) * AST + acol]),
                 A + (size_t)(brow + arow + r * 32) * K + k0 + acol);
            cp16(smaddr(&Bsv[s][(brw + r * 16) * BST + bcl]),
                 Bm + (size_t)(k0 + brw + r * 16) * N + bcol + bcl);
        }
        CP_COMMIT();
    }
    CP_WAIT(1);
    __syncthreads();

    int cur = 0;
    for (int kt = 0; kt < nk; kt++) {
        __half* Asc = Asv[cur];
        __half* Bsc = Bsv[cur];
        const int nxt2 = (cur + 2 >= 3) ? cur - 1 : cur + 2;
        if (kt + 2 < nk) {
            const int k0 = (kt + 2) << 6;
            #pragma unroll
            for (int r = 0; r < 4; r++) {
                cp16(smaddr(&Asv[nxt2][(arow + r * 32) * AST + acol]),
                     A + (size_t)(brow + arow + r * 32) * K + k0 + acol);
                cp16(smaddr(&Bsv[nxt2][(brw + r * 16) * BST + bcl]),
                     Bm + (size_t)(k0 + brw + r * 16) * N + bcol + bcl);
            }
            CP_COMMIT();
        }
        #pragma unroll
        for (int ks = 0; ks < 4; ks++) {
            uint32_t af[4][4], bf[4][2];
            const int koff = ks * 16 + ((lane >> 4) << 3);
            #pragma unroll
            for (int mt = 0; mt < 4; mt++)
                ldsm_x4(af[mt][0], af[mt][1], af[mt][2], af[mt][3],
                        smaddr(&Asc[(wm * 64 + mt * 16 + l15) * AST + koff]));
            #pragma unroll
            for (int np = 0; np < 2; np++)
                ldsm_x4t(bf[2*np][0], bf[2*np][1], bf[2*np+1][0], bf[2*np+1][1],
                         smaddr(&Bsc[(ks * 16 + l15) * BST + wn * 32 + np * 16 + ((lane >> 4) << 3)]));
            #pragma unroll
            for (int mt = 0; mt < 4; mt++)
                #pragma unroll
                for (int nt = 0; nt < 4; nt++)
                    MMA16(acc[mt][nt], af[mt][0], af[mt][1], af[mt][2], af[mt][3],
                          bf[nt][0], bf[nt][1]);
        }
        if (kt + 1 < nk) {
            if (kt + 2 < nk) { CP_WAIT(1); } else { CP_WAIT(0); }
        }
        __syncthreads();
        cur = (cur + 1 >= 3) ? 0 : cur + 1;
    }

    #pragma unroll
    for (int mt = 0; mt < 4; mt++) {
        #pragma unroll
        for (int half = 0; half < 2; half++) {
            const int row = brow + wm * 64 + mt * 16 + g + half * 8;
            #pragma unroll
            for (int nt = 0; nt < 4; nt++) {
                const int col = bcol + wn * 32 + nt * 8 + tg * 2;
                float v0 = acc[mt][nt][half * 2 + 0] + bias[col];
                float v1 = acc[mt][nt][half * 2 + 1] + bias[col + 1];
                if (EPI == 1) {
                    v0 = 0.5f * v0 * (1.0f + erff(v0 * 0.70710678118654752f));
                    v1 = 0.5f * v1 * (1.0f + erff(v1 * 0.70710678118654752f));
                }
                if (EPI == 2) {
                    float2 rr = *reinterpret_cast<const float2*>(res + (size_t)row * N + col);
                    v0 += rr.x; v1 += rr.y;
                }
                v0 *= oscale; v1 *= oscale;
                if (OUTH) {
                    *reinterpret_cast<uint32_t*>((__half*)C + (size_t)row * N + col) = h2pack(v0, v1);
                } else {
                    float2 o2; o2.x = v0; o2.y = v1;
                    *reinterpret_cast<float2*>((float*)C + (size_t)row * N + col) = o2;
                }
            }
        }
    }
}

template<int EPI, bool OUTH>
__global__ void __launch_bounds__(256, 2)
gemm_h(const __half* __restrict__ A, const __half* __restrict__ Bm,
       const float* __restrict__ bias, const float* __restrict__ res,
       void* __restrict__ C, int N, int K) {
    extern __shared__ __half smg[];
    __half* Ab = smg;
    __half* Bb = smg + 3 * A_BUF;
    gemm_body_h<EPI, OUTH>(A, Bm, bias, res, C, N, K, blockIdx.y * 128, blockIdx.x * 128, Ab, Bb, 1.0f);
}

// fused QKV: grid.x = 12 (8 q tiles, 2 k tiles, 2 v tiles)
#define QSCALE (0.125f * 1.4426950408889634f)
__global__ void __launch_bounds__(256, 2)
gemm_qkv(const __half* __restrict__ A,
         const __half* __restrict__ wq, const float* __restrict__ bq,
         const __half* __restrict__ wk, const float* __restrict__ bk,
         const __half* __restrict__ wv, const float* __restrict__ bv,
         __half* __restrict__ q, __half* __restrict__ k, __half* __restrict__ v) {
    extern __shared__ __half smg[];
    __half* Ab = smg;
    __half* Bb = smg + 3 * A_BUF;
    const int bx = blockIdx.x;
    const __half* Bm; const float* bias; __half* C; int N, bcol; float sc;
    if (bx < 8)       { Bm = wq; bias = bq; C = q; N = 1024; bcol = bx * 128;        sc = QSCALE; }
    else if (bx < 10) { Bm = wk; bias = bk; C = k; N = 256;  bcol = (bx - 8) * 128;  sc = 1.0f; }
    else              { Bm = wv; bias = bv; C = v; N = 256;  bcol = (bx - 10) * 128; sc = 1.0f; }
    gemm_body_h<0, true>(A, Bm, bias, nullptr, C, N, DD, blockIdx.y * 128, bcol, Ab, Bb, sc);
}

// ===================== Flash attention (fp16 mma, causal, GQA) =====================
#define QST 72
#define KST 72
#define VST 72
#define ATTN_HALVES (128*QST + 2*64*KST + 2*64*VST)

__global__ void __launch_bounds__(256, 2)
attn_h(const __half* __restrict__ Q, const __half* __restrict__ K,
       const __half* __restrict__ V, __half* __restrict__ O) {
    extern __shared__ __half smh[];
    __half* Qs = smh;
    __half* Ks = smh + 128 * QST;
    __half* Vs = Ks + 2 * 64 * KST;

    const int tid = threadIdx.x;
    const int lane = tid & 31, w = tid >> 5;
    const int g = lane >> 2, tg = lane & 3;
    const int l15 = lane & 15;
    const int h = blockIdx.y, b = blockIdx.z, grp = h >> 2;
    const int bx = (int)gridDim.x - 1 - (int)blockIdx.x;   // longest-work CTAs first
    const int q0 = bx << 7;

    {
        const size_t qbase = (size_t)(b * TT + q0) * DD + h * 64;
        #pragma unroll
        for (int i = 0; i < 4; i++) {
            const int f = tid + (i << 8);
            const int r = f >> 3, c = (f & 7) << 3;
            cp16(smaddr(&Qs[r * QST + c]), Q + qbase + (size_t)r * DD + c);
        }
    }
    {
        const size_t kvbase = (size_t)(b * TT) * 256 + grp * 64;
        #pragma unroll
        for (int i = 0; i < 2; i++) {
            const int f = tid + (i << 8);
            const int r = f >> 3, c = (f & 7) << 3;
            cp16(smaddr(&Ks[r * KST + c]), K + kvbase + (size_t)r * 256 + c);
            cp16(smaddr(&Vs[r * VST + c]), V + kvbase + (size_t)r * 256 + c);
        }
    }
    CP_COMMIT();
    CP_WAIT(0);
    __syncthreads();

    uint32_t qf[4][4];
    {
        const int koff = (lane >> 4) << 3;
        #pragma unroll
        for (int ks = 0; ks < 4; ks++)
            ldsm_x4(qf[ks][0], qf[ks][1], qf[ks][2], qf[ks][3],
                    smaddr(&Qs[(w * 16 + l15) * QST + ks * 16 + koff]));
    }

    float oacc[8][4];
    #pragma unroll
    for (int nt = 0; nt < 8; nt++)
        #pragma unroll
        for (int c = 0; c < 4; c++) oacc[nt][c] = 0.0f;
    float m0 = -1e30f, m1 = -1e30f, l0 = 0.0f, l1 = 0.0f;

    const int roww = q0 + w * 16;
    const int row0 = roww + g, row1 = roww + g + 8;

    const int jmax = 2 * bx + 1;
    for (int jt = 0; jt <= jmax; jt++) {
        const int cur = jt & 1;
        __half* Ksc = Ks + cur * (64 * KST);
        __half* Vsc = Vs + cur * (64 * VST);
        if (jt + 1 <= jmax) {
            __half* Ksn = Ks + (cur ^ 1) * (64 * KST);
            __half* Vsn = Vs + (cur ^ 1) * (64 * VST);
            const size_t kvbase = (size_t)(b * TT + ((jt + 1) << 6)) * 256 + grp * 64;
            #pragma unroll
            for (int i = 0; i < 2; i++) {
                const int f = tid + (i << 8);
                const int r = f >> 3, c = (f & 7) << 3;
                cp16(smaddr(&Ksn[r * KST + c]), K + kvbase + (size_t)r * 256 + c);
                cp16(smaddr(&Vsn[r * VST + c]), V + kvbase + (size_t)r * 256 + c);
            }
            CP_COMMIT();
        }

        const int ktile0 = jt << 6;
        if (ktile0 <= roww + 15) {
            // ---- S = Q K^T (log2e domain) ----
            float sacc[8][4];
            #pragma unroll
            for (int nt = 0; nt < 8; nt++)
                #pragma unroll
                for (int c = 0; c < 4; c++) sacc[nt][c] = 0.0f;
            #pragma unroll
            for (int ks = 0; ks < 4; ks++) {
                const int kc = ks * 16 + (((lane >> 3) & 1) << 3);
                #pragma unroll
                for (int np = 0; np < 4; np++) {
                    uint32_t b0e, b1e, b0o, b1o;
                    ldsm_x4(b0e, b1e, b0o, b1o,
                            smaddr(&Ksc[(np * 16 + ((lane >> 4) << 3) + (lane & 7)) * KST + kc]));
                    MMA16(sacc[2*np],   qf[ks][0], qf[ks][1], qf[ks][2], qf[ks][3], b0e, b1e);
                    MMA16(sacc[2*np+1], qf[ks][0], qf[ks][1], qf[ks][2], qf[ks][3], b0o, b1o);
                }
            }

            if (ktile0 + 63 > roww) {
                #pragma unroll
                for (int nt = 0; nt < 8; nt++) {
                    const int c0 = ktile0 + nt * 8 + 2 * tg;
                    if (c0 > row0)     sacc[nt][0] = -1e30f;
                    if (c0 + 1 > row0) sacc[nt][1] = -1e30f;
                    if (c0 > row1)     sacc[nt][2] = -1e30f;
                    if (c0 + 1 > row1) sacc[nt][3] = -1e30f;
                }
            }

            float tm0 = -1e30f, tm1 = -1e30f;
            #pragma unroll
            for (int nt = 0; nt < 8; nt++) {
                tm0 = fmaxf(tm0, fmaxf(sacc[nt][0], sacc[nt][1]));
                tm1 = fmaxf(tm1, fmaxf(sacc[nt][2], sacc[nt][3]));
            }
            #pragma unroll
            for (int off = 1; off <= 2; off <<= 1) {
                tm0 = fmaxf(tm0, __shfl_xor_sync(0xffffffffu, tm0, off));
                tm1 = fmaxf(tm1, __shfl_xor_sync(0xffffffffu, tm1, off));
            }
            const float nm0 = fmaxf(m0, tm0), nm1 = fmaxf(m1, tm1);
            const float al0 = ex2f(m0 - nm0), al1 = ex2f(m1 - nm1);
            m0 = nm0; m1 = nm1;
            float ts0 = 0.0f, ts1 = 0.0f;
            #pragma unroll
            for (int nt = 0; nt < 8; nt++) {
                sacc[nt][0] = ex2f(sacc[nt][0] - nm0);
                sacc[nt][1] = ex2f(sacc[nt][1] - nm0);
                sacc[nt][2] = ex2f(sacc[nt][2] - nm1);
                sacc[nt][3] = ex2f(sacc[nt][3] - nm1);
                ts0 += sacc[nt][0] + sacc[nt][1];
                ts1 += sacc[nt][2] + sacc[nt][3];
            }
            #pragma unroll
            for (int off = 1; off <= 2; off <<= 1) {
                ts0 += __shfl_xor_sync(0xffffffffu, ts0, off);
                ts1 += __shfl_xor_sync(0xffffffffu, ts1, off);
            }
            l0 = l0 * al0 + ts0;
            l1 = l1 * al1 + ts1;
            #pragma unroll
            for (int nt = 0; nt < 8; nt++) {
                oacc[nt][0] *= al0; oacc[nt][1] *= al0;
                oacc[nt][2] *= al1; oacc[nt][3] *= al1;
            }

            // ---- O += P @ V (register repack, x4t V loads) ----
            #pragma unroll
            for (int ks = 0; ks < 4; ks++) {
                const uint32_t a0 = h2pack(sacc[2*ks][0],   sacc[2*ks][1]);
                const uint32_t a1 = h2pack(sacc[2*ks][2],   sacc[2*ks][3]);
                const uint32_t a2 = h2pack(sacc[2*ks+1][0], sacc[2*ks+1][1]);
                const uint32_t a3 = h2pack(sacc[2*ks+1][2], sacc[2*ks+1][3]);
                #pragma unroll
                for (int np = 0; np < 4; np++) {
                    uint32_t b0e, b1e, b0o, b1o;
                    ldsm_x4t(b0e, b1e, b0o, b1o,
                             smaddr(&Vsc[(ks * 16 + l15) * VST + np * 16 + ((lane >> 4) << 3)]));
                    MMA16(oacc[2*np],   a0, a1, a2, a3, b0e, b1e);
                    MMA16(oacc[2*np+1], a0, a1, a2, a3, b0o, b1o);
                }
            }
        }
        if (jt + 1 <= jmax) CP_WAIT(0);
        __syncthreads();
    }

    const float inv0 = 1.0f / l0, inv1 = 1.0f / l1;
    const size_t ob0 = (size_t)(b * TT + row0) * DD + h * 64;
    const size_t ob1 = (size_t)(b * TT + row1) * DD + h * 64;
    #pragma unroll
    for (int nt = 0; nt < 8; nt++) {
        const int col = nt * 8 + 2 * tg;
        *reinterpret_cast<uint32_t*>(O + ob0 + col) = h2pack(oacc[nt][0] * inv0, oacc[nt][1] * inv0);
        *reinterpret_cast<uint32_t*>(O + ob1 + col) = h2pack(oacc[nt][2] * inv1, oacc[nt][3] * inv1);
    }
}

// ===================== launch =====================
extern "C" void kernel_launch(void* const* d_in, const int* in_sizes, int n_in,
                              void* d_out, int out_size) {
    (void)in_sizes; (void)n_in; (void)out_size;
    const float* x   = (const float*)d_in[0];
    const float* g1  = (const float*)d_in[1];
    const float* bt1 = (const float*)d_in[2];
    const float* wq  = (const float*)d_in[3];
    const float* bq  = (const float*)d_in[4];
    const float* wk  = (const float*)d_in[5];
    const float* bk  = (const float*)d_in[6];
    const float* wv  = (const float*)d_in[7];
    const float* bv  = (const float*)d_in[8];
    const float* wo  = (const float*)d_in[9];
    const float* bo  = (const float*)d_in[10];
    const float* g2  = (const float*)d_in[11];
    const float* bt2 = (const float*)d_in[12];
    const float* w1  = (const float*)d_in[13];
    const float* b1  = (const float*)d_in[14];
    const float* w2  = (const float*)d_in[15];
    const float* b2  = (const float*)d_in[16];
    float* out = (float*)d_out;

    __half *h1, *q, *k, *v, *ao, *h2, *f1;
    float* x1;
    __half *hwq, *hwk, *hwv, *hwo, *hw1, *hw2;
    cudaGetSymbolAddress((void**)&h1, g_h1);
    cudaGetSymbolAddress((void**)&q,  g_q);
    cudaGetSymbolAddress((void**)&k,  g_k);
    cudaGetSymbolAddress((void**)&v,  g_v);
    cudaGetSymbolAddress((void**)&ao, g_ao);
    cudaGetSymbolAddress((void**)&x1, g_x1);
    cudaGetSymbolAddress((void**)&h2, g_h2);
    cudaGetSymbolAddress((void**)&f1, g_f1);
    cudaGetSymbolAddress((void**)&hwq, g_wq);
    cudaGetSymbolAddress((void**)&hwk, g_wk);
    cudaGetSymbolAddress((void**)&hwv, g_wv);
    cudaGetSymbolAddress((void**)&hwo, g_wo);
    cudaGetSymbolAddress((void**)&hw1, g_w1);
    cudaGetSymbolAddress((void**)&hw2, g_w2);

    const int ATTN_SMEM = ATTN_HALVES * (int)sizeof(__half);
    cudaFuncSetAttribute(attn_h, cudaFuncAttributeMaxDynamicSharedMemorySize, ATTN_SMEM);
    cudaFuncSetAttribute(gemm_h<0, true>,  cudaFuncAttributeMaxDynamicSharedMemorySize, GEMM_SMEM);
    cudaFuncSetAttribute(gemm_h<1, true>,  cudaFuncAttributeMaxDynamicSharedMemorySize, GEMM_SMEM);
    cudaFuncSetAttribute(gemm_h<2, false>, cudaFuncAttributeMaxDynamicSharedMemorySize, GEMM_SMEM);
    cudaFuncSetAttribute(gemm_qkv,         cudaFuncAttributeMaxDynamicSharedMemorySize, GEMM_SMEM);

    // 0. weights fp32 -> fp16
    cvt_w<<<(C5 + 255) / 256, 256>>>(wq, wk, wv, wo, w1, w2, hwq, hwk, hwv, hwo, hw1, hw2);
    // 1. h1 = LN(x)
    ln_kernel<<<RR, 256>>>(x, g1, bt1, h1);
    // 2. fused q/k/v (q pre-scaled by 0.125*log2e)
    gemm_qkv<<<dim3(12, RR / 128), 256, GEMM_SMEM>>>(h1, hwq, bq, hwk, bk, hwv, bv, q, k, v);
    // 3. attention
    attn_h<<<dim3(TT / 128, 16, BB), 256, ATTN_SMEM>>>(q, k, v, ao);
    // 4. x1 = x + ao @ wo + bo   (fp32 out)
    gemm_h<2, false><<<dim3(DD / 128, RR / 128), 256, GEMM_SMEM>>>(ao, hwo, bo, x, x1, DD, DD);
    // 5. h2 = LN(x1)
    ln_kernel<<<RR, 256>>>(x1, g2, bt2, h2);
    // 6. f1 = gelu(h2 @ w1 + b1)  (fp16 out)
    gemm_h<1, true><<<dim3(4 * DD / 128, RR / 128), 256, GEMM_SMEM>>>(h2, hw1, b1, nullptr, f1, 4 * DD, DD);
    // 7. out = x1 + f1 @ w2 + b2  (fp32 out)
    gemm_h<2, false><<<dim3(DD / 128, RR / 128), 256, GEMM_SMEM>>>(f1, hw2, b2, x1, out, DD, 4 * DD);
}